// round 1
// baseline (speedup 1.0000x reference)
#include <cuda_runtime.h>
#include <math.h>

#define D_    1024
#define BATCH 4
#define NB_   2048
#define NCTX  2048
#define H_    16
#define HD_   64
#define E_    8
#define NTOK  8192

// ---------------- scratch (device globals; no allocation allowed) ----------------
__device__ float g_ctxAC[NTOK * D_];
__device__ float g_q[NTOK * D_];
__device__ float g_kv[NTOK * 2 * D_];
__device__ float g_attn[NTOK * D_];
__device__ float g_proj[NTOK * D_];
__device__ float g_ctxB[NTOK * D_];
__device__ float g_hidden[NTOK * D_];
__device__ float g_logits[NTOK * E_];
__device__ float g_emb[BATCH * D_];
__device__ float g_h2[BATCH * 2 * D_];
__device__ float g_temb[BATCH * D_];
__device__ float g_tec[BATCH * D_];
__device__ float g_loadp[32 * E_];

// ---------------- SGEMM: C(MxN) = A(MxK,lda) * B(NxK,ldb)^T (+epilogue) ----------
template <bool ACCUM, bool RELU>
__global__ void __launch_bounds__(256, 2) sgemm_nt(
    int M, int N, int K,
    const float* __restrict__ A, int lda,
    const float* __restrict__ B, int ldb,
    float* __restrict__ C,
    const float* __restrict__ colBias,
    const float* __restrict__ batchBias)
{
    __shared__ float As[8][128];
    __shared__ float Bs[8][128];
    const int tid = threadIdx.x;
    const int bm = blockIdx.y * 128, bn = blockIdx.x * 128;
    const int lr = tid >> 1;
    const int lc = (tid & 1) * 4;
    const float* Ag = A + (long)(bm + lr) * lda + lc;
    const float* Bg = B + (long)(bn + lr) * ldb + lc;
    const int ty = tid >> 4, tx = tid & 15;

    float acc[8][8];
#pragma unroll
    for (int i = 0; i < 8; i++)
#pragma unroll
        for (int j = 0; j < 8; j++) acc[i][j] = 0.f;

    for (int k0 = 0; k0 < K; k0 += 8) {
        float4 av = *(const float4*)(Ag + k0);
        float4 bv = *(const float4*)(Bg + k0);
        __syncthreads();
        As[lc + 0][lr] = av.x; As[lc + 1][lr] = av.y;
        As[lc + 2][lr] = av.z; As[lc + 3][lr] = av.w;
        Bs[lc + 0][lr] = bv.x; Bs[lc + 1][lr] = bv.y;
        Bs[lc + 2][lr] = bv.z; Bs[lc + 3][lr] = bv.w;
        __syncthreads();
#pragma unroll
        for (int k = 0; k < 8; k++) {
            float ra[8], rb[8];
            *(float4*)(ra)     = *(const float4*)&As[k][ty * 8];
            *(float4*)(ra + 4) = *(const float4*)&As[k][ty * 8 + 4];
            *(float4*)(rb)     = *(const float4*)&Bs[k][tx * 8];
            *(float4*)(rb + 4) = *(const float4*)&Bs[k][tx * 8 + 4];
#pragma unroll
            for (int i = 0; i < 8; i++)
#pragma unroll
                for (int j = 0; j < 8; j++)
                    acc[i][j] += ra[i] * rb[j];
        }
    }

    const int brow = bm + ty * 8;
    const int bcol = bn + tx * 8;
    const float* bb = batchBias ? (batchBias + (long)(bm >> 11) * N) : nullptr;
#pragma unroll
    for (int i = 0; i < 8; i++) {
        long rbase = (long)(brow + i) * N;
#pragma unroll
        for (int j = 0; j < 8; j += 4) {
            int c = bcol + j;
            float4 v = make_float4(acc[i][j], acc[i][j + 1], acc[i][j + 2], acc[i][j + 3]);
            if (colBias) {
                v.x += colBias[c]; v.y += colBias[c + 1];
                v.z += colBias[c + 2]; v.w += colBias[c + 3];
            }
            if (bb) {
                v.x += bb[c]; v.y += bb[c + 1];
                v.z += bb[c + 2]; v.w += bb[c + 3];
            }
            if (ACCUM) {
                float4 o = *(const float4*)&C[rbase + c];
                v.x += o.x; v.y += o.y; v.z += o.z; v.w += o.w;
            }
            if (RELU) {
                v.x = fmaxf(v.x, 0.f); v.y = fmaxf(v.y, 0.f);
                v.z = fmaxf(v.z, 0.f); v.w = fmaxf(v.w, 0.f);
            }
            *(float4*)&C[rbase + c] = v;
        }
    }
}

// ---------------- flash attention (fp32, 64x64 tiles) ----------------------------
#define SMS 65
__global__ void __launch_bounds__(256) flash_kernel(
    const float* __restrict__ Q, const float* __restrict__ KV, float* __restrict__ O)
{
    extern __shared__ float sm[];
    float* Qs = sm;
    float* Ks = Qs + 64 * SMS;
    float* Vs = Ks + 64 * SMS;
    float* Ps = Vs + 64 * SMS;

    const int tid = threadIdx.x;
    const int bh = blockIdx.y, b = bh >> 4, h = bh & 15;
    const int q0 = blockIdx.x * 64;
    const int r = tid >> 2, c0 = (tid & 3) * 16;

    // load Q tile (64 rows x 64 cols of the head slice)
    {
        const float* qg = Q + (long)(b * NB_ + q0 + r) * D_ + h * HD_ + c0;
        float4 t0 = *(const float4*)(qg);
        float4 t1 = *(const float4*)(qg + 4);
        float4 t2 = *(const float4*)(qg + 8);
        float4 t3 = *(const float4*)(qg + 12);
        float* d = Qs + r * SMS + c0;
        d[0] = t0.x; d[1] = t0.y; d[2] = t0.z; d[3] = t0.w;
        d[4] = t1.x; d[5] = t1.y; d[6] = t1.z; d[7] = t1.w;
        d[8] = t2.x; d[9] = t2.y; d[10] = t2.z; d[11] = t2.w;
        d[12] = t3.x; d[13] = t3.y; d[14] = t3.z; d[15] = t3.w;
    }

    const int ty = tid >> 4, tx = tid & 15;
    float m[4], l[4], o[4][4];
#pragma unroll
    for (int i = 0; i < 4; i++) {
        m[i] = -1e30f; l[i] = 0.f;
#pragma unroll
        for (int j = 0; j < 4; j++) o[i][j] = 0.f;
    }

    const float* kg = KV + (long)b * NCTX * 2048 + h * HD_ + c0;

    for (int kt = 0; kt < NCTX; kt += 64) {
        __syncthreads();
        {
            const float* krow = kg + (long)(kt + r) * 2048;
            float4 t0 = *(const float4*)(krow);
            float4 t1 = *(const float4*)(krow + 4);
            float4 t2 = *(const float4*)(krow + 8);
            float4 t3 = *(const float4*)(krow + 12);
            float* d = Ks + r * SMS + c0;
            d[0] = t0.x; d[1] = t0.y; d[2] = t0.z; d[3] = t0.w;
            d[4] = t1.x; d[5] = t1.y; d[6] = t1.z; d[7] = t1.w;
            d[8] = t2.x; d[9] = t2.y; d[10] = t2.z; d[11] = t2.w;
            d[12] = t3.x; d[13] = t3.y; d[14] = t3.z; d[15] = t3.w;
            const float* vrow = krow + 1024;
            t0 = *(const float4*)(vrow);
            t1 = *(const float4*)(vrow + 4);
            t2 = *(const float4*)(vrow + 8);
            t3 = *(const float4*)(vrow + 12);
            d = Vs + r * SMS + c0;
            d[0] = t0.x; d[1] = t0.y; d[2] = t0.z; d[3] = t0.w;
            d[4] = t1.x; d[5] = t1.y; d[6] = t1.z; d[7] = t1.w;
            d[8] = t2.x; d[9] = t2.y; d[10] = t2.z; d[11] = t2.w;
            d[12] = t3.x; d[13] = t3.y; d[14] = t3.z; d[15] = t3.w;
        }
        __syncthreads();

        float S[4][4];
#pragma unroll
        for (int i = 0; i < 4; i++)
#pragma unroll
            for (int j = 0; j < 4; j++) S[i][j] = 0.f;

#pragma unroll 8
        for (int k = 0; k < 64; k++) {
            float qr[4], kr[4];
#pragma unroll
            for (int i = 0; i < 4; i++) qr[i] = Qs[(ty + 16 * i) * SMS + k];
#pragma unroll
            for (int j = 0; j < 4; j++) kr[j] = Ks[(tx + 16 * j) * SMS + k];
#pragma unroll
            for (int i = 0; i < 4; i++)
#pragma unroll
                for (int j = 0; j < 4; j++)
                    S[i][j] += qr[i] * kr[j];
        }

        // online softmax (rows ty+16*i; 16-lane row groups)
#pragma unroll
        for (int i = 0; i < 4; i++) {
            float mx = -1e30f;
#pragma unroll
            for (int j = 0; j < 4; j++) { S[i][j] *= 0.125f; mx = fmaxf(mx, S[i][j]); }
#pragma unroll
            for (int off = 8; off > 0; off >>= 1)
                mx = fmaxf(mx, __shfl_xor_sync(0xffffffffu, mx, off, 16));
            float mn = fmaxf(m[i], mx);
            float al = expf(m[i] - mn);
            float s = 0.f;
#pragma unroll
            for (int j = 0; j < 4; j++) { S[i][j] = expf(S[i][j] - mn); s += S[i][j]; }
#pragma unroll
            for (int off = 8; off > 0; off >>= 1)
                s += __shfl_xor_sync(0xffffffffu, s, off, 16);
            l[i] = l[i] * al + s;
            m[i] = mn;
#pragma unroll
            for (int j = 0; j < 4; j++) o[i][j] *= al;
        }

#pragma unroll
        for (int i = 0; i < 4; i++)
#pragma unroll
            for (int j = 0; j < 4; j++)
                Ps[(ty + 16 * i) * SMS + tx + 16 * j] = S[i][j];
        __syncthreads();

#pragma unroll 8
        for (int k = 0; k < 64; k++) {
            float pr[4], vr[4];
#pragma unroll
            for (int i = 0; i < 4; i++) pr[i] = Ps[(ty + 16 * i) * SMS + k];
#pragma unroll
            for (int j = 0; j < 4; j++) vr[j] = Vs[k * SMS + tx + 16 * j];
#pragma unroll
            for (int i = 0; i < 4; i++)
#pragma unroll
                for (int j = 0; j < 4; j++)
                    o[i][j] += pr[i] * vr[j];
        }
    }

    float* og = O + (long)(b * NB_ + q0) * D_ + h * HD_;
#pragma unroll
    for (int i = 0; i < 4; i++) {
        float inv = 1.0f / l[i];
#pragma unroll
        for (int j = 0; j < 4; j++)
            og[(long)(ty + 16 * i) * D_ + tx + 16 * j] = o[i][j] * inv;
    }
}

// ---------------- residual + layernorm ------------------------------------------
__global__ void __launch_bounds__(256) ln_kernel(
    const float* __restrict__ X, const float* __restrict__ R,
    const float* __restrict__ gam, const float* __restrict__ bet, float* __restrict__ Y)
{
    __shared__ float red[8];
    const int row = blockIdx.x, tid = threadIdx.x;
    const float* x = X + (long)row * D_;
    const float* rr = R + (long)row * D_;
    float v[4];
    float s = 0.f;
#pragma unroll
    for (int i = 0; i < 4; i++) {
        int c = tid + 256 * i;
        v[i] = x[c] + rr[c];
        s += v[i];
    }
#pragma unroll
    for (int off = 16; off > 0; off >>= 1) s += __shfl_xor_sync(0xffffffffu, s, off);
    if ((tid & 31) == 0) red[tid >> 5] = s;
    __syncthreads();
    float tot = red[0] + red[1] + red[2] + red[3] + red[4] + red[5] + red[6] + red[7];
    float mu = tot * (1.0f / 1024.0f);
    __syncthreads();
    float s2 = 0.f;
#pragma unroll
    for (int i = 0; i < 4; i++) { float d = v[i] - mu; s2 += d * d; }
#pragma unroll
    for (int off = 16; off > 0; off >>= 1) s2 += __shfl_xor_sync(0xffffffffu, s2, off);
    if ((tid & 31) == 0) red[tid >> 5] = s2;
    __syncthreads();
    float tot2 = red[0] + red[1] + red[2] + red[3] + red[4] + red[5] + red[6] + red[7];
    float rstd = rsqrtf(tot2 * (1.0f / 1024.0f) + 1e-5f);
#pragma unroll
    for (int i = 0; i < 4; i++) {
        int c = tid + 256 * i;
        Y[(long)row * D_ + c] = (v[i] - mu) * rstd * gam[c] + bet[c];
    }
}

// ---------------- generic warp-dot: Y[b][j] = act(dot(X[b], W[j]) + b1 + b2) ------
template <int ACT>  // 0 none, 1 silu
__global__ void __launch_bounds__(256) rowdot(
    const float* __restrict__ X, const float* __restrict__ W, int ldw,
    const float* __restrict__ b1, const float* __restrict__ b2,
    float* __restrict__ Y, int Kd, int J)
{
    const int b = blockIdx.x;
    const int w = threadIdx.x >> 5, lane = threadIdx.x & 31;
    const int j = blockIdx.y * 8 + w;
    const float* x = X + (long)b * Kd;
    const float* wr = W + (long)j * ldw;
    float s = 0.f;
    for (int k = lane * 4; k < Kd; k += 128) {
        float4 xv = *(const float4*)(x + k);
        float4 wv = *(const float4*)(wr + k);
        s += xv.x * wv.x + xv.y * wv.y + xv.z * wv.z + xv.w * wv.w;
    }
#pragma unroll
    for (int off = 16; off > 0; off >>= 1) s += __shfl_xor_sync(0xffffffffu, s, off);
    if (lane == 0) {
        if (b1) s += b1[j];
        if (b2) s += b2[j];
        if (ACT == 1) s = s / (1.f + expf(-s));
        Y[(long)b * J + j] = s;
    }
}

// ---------------- small kernels ---------------------------------------------------
__global__ void emb_kernel(const int* __restrict__ t)
{
    const int b = blockIdx.x, i = threadIdx.x;  // 512 threads
    float fr = expf(-9.2103403719761836f * (float)i / 511.0f);
    float arg = (float)t[b] * fr;
    g_emb[b * D_ + i] = sinf(arg);
    g_emb[b * D_ + 512 + i] = cosf(arg);
}

__global__ void __launch_bounds__(256) concat_kernel(
    const float* __restrict__ A, const float* __restrict__ C)
{
    const int row = blockIdx.x;
    const int b = row >> 11, j = row & 2047;
    const float* src = (j < 1024) ? (A + ((long)b * 1024 + j) * D_)
                                  : (C + ((long)b * 1024 + (j - 1024)) * D_);
    float4* dst = (float4*)(g_ctxAC + (long)row * D_);
    dst[threadIdx.x] = ((const float4*)src)[threadIdx.x];
}

__global__ void __launch_bounds__(256) router_kernel(
    const float* __restrict__ logits, const int* __restrict__ t,
    float* __restrict__ dispatch, float* __restrict__ combine, float* __restrict__ loadp)
{
    __shared__ float sd[8 * 256];
    const int tid = threadIdx.x;
    const int tok = blockIdx.x * 256 + tid;
    const int b = tok >> 11;
    const float tn = (float)t[b] * 0.001f;
    const float tau_inv = 1.0f / (0.5f + 1.5f * tn);

    float p[8];
    float mx = -1e30f;
#pragma unroll
    for (int e = 0; e < 8; e++) { p[e] = logits[tok * 8 + e] * tau_inv; mx = fmaxf(mx, p[e]); }
    float s = 0.f;
#pragma unroll
    for (int e = 0; e < 8; e++) { p[e] = expf(p[e] - mx); s += p[e]; }
    float inv = 1.0f / s;
#pragma unroll
    for (int e = 0; e < 8; e++) p[e] = 0.85f * (p[e] * inv) + 0.01875f;

    const float w = 0.1f + 0.1f * tn;
    float sh = fmaxf(p[0], w);
    float os = 0.f;
#pragma unroll
    for (int e = 1; e < 8; e++) os += p[e];
    float sc = (1.0f - sh) / fmaxf(os, 1e-8f);
    p[0] = sh;
#pragma unroll
    for (int e = 1; e < 8; e++) p[e] *= sc;

    int i1 = 0; float v1 = p[0];
#pragma unroll
    for (int e = 1; e < 8; e++) if (p[e] > v1) { v1 = p[e]; i1 = e; }
    int i2 = -1; float v2 = -1e30f;
#pragma unroll
    for (int e = 0; e < 8; e++) if (e != i1 && p[e] > v2) { v2 = p[e]; i2 = e; }

    float d[8];
#pragma unroll
    for (int e = 0; e < 8; e++) d[e] = 0.f;
    d[i1] = v1; d[i2] = v2;

    const float cap = 0.5f + 0.1f * tn;
    float ext = 0.f, hs = 0.f;
    float hd[8];
#pragma unroll
    for (int e = 0; e < 8; e++) {
        float ex = fmaxf(d[e] - cap, 0.f);
        d[e] -= ex; ext += ex;
        hd[e] = fmaxf(cap - d[e], 0.f); hs += hd[e];
    }
    hs = fmaxf(hs, 1e-8f);
    float ds = 0.f;
#pragma unroll
    for (int e = 0; e < 8; e++) { d[e] += ext * (hd[e] / hs); ds += d[e]; }
    float ci = 1.0f / (ds + 1e-8f);
#pragma unroll
    for (int e = 0; e < 8; e++) {
        dispatch[tok * 8 + e] = d[e];
        combine[tok * 8 + e] = d[e] * ci;
        sd[e * 256 + tid] = d[e];
    }
    __syncthreads();
    if (tid < 8) {
        float acc = 0.f;
        for (int i = 0; i < 256; i++) acc += sd[tid * 256 + i];
        loadp[blockIdx.x * 8 + tid] = acc;  // deterministic per-block partial
    }
}

__global__ void penalty_kernel(const float* __restrict__ loadp, float* __restrict__ out)
{
    if (threadIdx.x == 0) {
        const float thr = (2048.0f / 7.0f) * 1.5f;
        float pen = 0.f;
        for (int e = 1; e < 8; e++) {
            float l = 0.f;
            for (int blk = 0; blk < 32; blk++) l += loadp[blk * 8 + e];
            l *= 0.25f;  // sum over tokens per batch, mean over 4 batches
            float x = l - thr;
            if (x > 0.f) pen += x * x;
        }
        out[0] = 0.01f * pen;
    }
}

// ---------------- launch ----------------------------------------------------------
extern "C" void kernel_launch(void* const* d_in, const int* in_sizes, int n_in,
                              void* d_out, int out_size)
{
    const float* tokens = (const float*)d_in[0];
    const float* outA   = (const float*)d_in[1];
    const float* outC   = (const float*)d_in[2];
    const int*   t      = (const int*)d_in[3];
    const float* in_w   = (const float*)d_in[4];
    const float* in_b   = (const float*)d_in[5];
    const float* op_w   = (const float*)d_in[6];
    const float* op_b   = (const float*)d_in[7];
    const float* lng    = (const float*)d_in[8];
    const float* lnb    = (const float*)d_in[9];
    const float* te_w1  = (const float*)d_in[10];
    const float* te_b1  = (const float*)d_in[11];
    const float* te_w2  = (const float*)d_in[12];
    const float* te_b2  = (const float*)d_in[13];
    const float* gw1    = (const float*)d_in[14];
    const float* gb1    = (const float*)d_in[15];
    const float* gw2    = (const float*)d_in[16];
    const float* gb2    = (const float*)d_in[17];
    const float* ebias  = (const float*)d_in[18];
    float* out = (float*)d_out;

    float *p_ctxAC, *p_q, *p_kv, *p_attn, *p_proj, *p_ctxB, *p_hidden,
          *p_logits, *p_emb, *p_h2, *p_temb, *p_tec, *p_loadp;
    cudaGetSymbolAddress((void**)&p_ctxAC, g_ctxAC);
    cudaGetSymbolAddress((void**)&p_q, g_q);
    cudaGetSymbolAddress((void**)&p_kv, g_kv);
    cudaGetSymbolAddress((void**)&p_attn, g_attn);
    cudaGetSymbolAddress((void**)&p_proj, g_proj);
    cudaGetSymbolAddress((void**)&p_ctxB, g_ctxB);
    cudaGetSymbolAddress((void**)&p_hidden, g_hidden);
    cudaGetSymbolAddress((void**)&p_logits, g_logits);
    cudaGetSymbolAddress((void**)&p_emb, g_emb);
    cudaGetSymbolAddress((void**)&p_h2, g_h2);
    cudaGetSymbolAddress((void**)&p_temb, g_temb);
    cudaGetSymbolAddress((void**)&p_tec, g_tec);
    cudaGetSymbolAddress((void**)&p_loadp, g_loadp);

    cudaFuncSetAttribute(flash_kernel, cudaFuncAttributeMaxDynamicSharedMemorySize,
                         4 * 64 * SMS * (int)sizeof(float));

    // ---- time embedding chain (tiny; independent of everything but t) ----
    emb_kernel<<<BATCH, 512>>>(t);
    rowdot<1><<<dim3(BATCH, 256), 256>>>(p_emb, te_w1, 1024, te_b1, nullptr, p_h2, 1024, 2048);
    rowdot<0><<<dim3(BATCH, 128), 256>>>(p_h2, te_w2, 2048, te_b2, nullptr, p_temb, 2048, 1024);
    // te contribution to gate hidden (+gate_b1 folded in)
    rowdot<0><<<dim3(BATCH, 128), 256>>>(p_temb, gw1 + 2048, 3072, gb1, nullptr, p_tec, 1024, 1024);

    // ---- attention path ----
    concat_kernel<<<NTOK, 256>>>(outA, outC);
    sgemm_nt<false, false><<<dim3(8, 64), 256>>>(NTOK, 1024, 1024, tokens, 1024,
                                                 in_w, 1024, p_q, in_b, nullptr);
    sgemm_nt<false, false><<<dim3(16, 64), 256>>>(NTOK, 2048, 1024, p_ctxAC, 1024,
                                                  in_w + 1024 * 1024, 1024, p_kv,
                                                  in_b + 1024, nullptr);
    flash_kernel<<<dim3(32, BATCH * H_), 256, 4 * 64 * SMS * sizeof(float)>>>(p_q, p_kv, p_attn);
    sgemm_nt<false, false><<<dim3(8, 64), 256>>>(NTOK, 1024, 1024, p_attn, 1024,
                                                 op_w, 1024, p_proj, op_b, nullptr);
    ln_kernel<<<NTOK, 256>>>(p_proj, tokens, lng, lnb, p_ctxB);

    // ---- gate hidden: relu(tokens@W1a^T + ctxB@W1b^T + te_contrib) ----
    sgemm_nt<false, false><<<dim3(8, 64), 256>>>(NTOK, 1024, 1024, tokens, 1024,
                                                 gw1, 3072, p_hidden, nullptr, p_tec);
    sgemm_nt<true, true><<<dim3(8, 64), 256>>>(NTOK, 1024, 1024, p_ctxB, 1024,
                                               gw1 + 1024, 3072, p_hidden, nullptr, nullptr);

    // ---- logits + routing ----
    rowdot<0><<<dim3(NTOK, 1), 256>>>(p_hidden, gw2, 1024, gb2, ebias, p_logits, 1024, 8);
    router_kernel<<<32, 256>>>(p_logits, t, out, out + 65536, p_loadp);
    penalty_kernel<<<1, 32>>>(p_loadp, out + 2 * 65536);
}

// round 3
// speedup vs baseline: 1.1477x; 1.1477x over previous
#include <cuda_runtime.h>
#include <math.h>
#include <stdint.h>

#define D_    1024
#define BATCH 4
#define NB_   2048
#define NCTX  2048
#define H_    16
#define HD_   64
#define E_    8
#define NTOK  8192

// ---------------- scratch (device globals; no allocation allowed) ----------------
__device__ float g_ctxAC[NTOK * D_];
__device__ float g_q[NTOK * D_];
__device__ float g_kv[NTOK * 2 * D_];
__device__ float g_attn[NTOK * D_];
__device__ float g_proj[NTOK * D_];
__device__ float g_ctxB[NTOK * D_];
__device__ float g_hidden[NTOK * D_];
__device__ float g_logits[NTOK * E_];
__device__ float g_emb[BATCH * D_];
__device__ float g_h2[BATCH * 2 * D_];
__device__ float g_temb[BATCH * D_];
__device__ float g_tec[BATCH * D_];
__device__ float g_loadp[32 * E_];

// ================= tf32 helpers ==================================================
__device__ __forceinline__ float f2tf32(float x) {
    uint32_t r;
    asm("cvt.rna.tf32.f32 %0, %1;" : "=r"(r) : "f"(x));
    return __uint_as_float(r);
}
__device__ __forceinline__ void mma8(float* d, const float4 a, const float2 b) {
    asm volatile(
        "mma.sync.aligned.m16n8k8.row.col.f32.tf32.tf32.f32 "
        "{%0,%1,%2,%3}, {%4,%5,%6,%7}, {%8,%9}, {%0,%1,%2,%3};\n"
        : "+f"(d[0]), "+f"(d[1]), "+f"(d[2]), "+f"(d[3])
        : "r"(__float_as_uint(a.x)), "r"(__float_as_uint(a.y)),
          "r"(__float_as_uint(a.z)), "r"(__float_as_uint(a.w)),
          "r"(__float_as_uint(b.x)), "r"(__float_as_uint(b.y)));
}

// Buffer layout (floats): Ah[4096] Al[4096] Bh[4096] Bl[4096] ; two buffers.
#define TGEMM_SMEM (2 * 16384 * 4)

// ============= 3xTF32 mma.sync GEMM: C(MxN) = A(MxK)*B(NxK)^T + epilogue =========
// grid=(N/128, M/128), 256 threads, 8 warps (2M x 4N), warp tile 64x32, K%32==0.
// A/B staged in registers, converted to tf32 hi/lo, stored to smem in exact
// m16n8k8 fragment layout (LDS.128 / LDS.64 conflict-free reads).
template <bool ACCUM, bool RELU>
__global__ void __launch_bounds__(256) tgemm_nt(
    int N, int K,
    const float* __restrict__ A, int lda,
    const float* __restrict__ B, int ldb,
    float* __restrict__ C,
    const float* __restrict__ colBias,
    const float* __restrict__ batchBias)
{
    extern __shared__ float sm[];
    const int tid = threadIdx.x, wid = tid >> 5, lane = tid & 31;
    const int g = lane >> 2, tg = lane & 3;
    const int bm = blockIdx.y * 128, bn = blockIdx.x * 128;
    const int wm = wid & 1, wn = wid >> 1;

    float c[4][4][4];
#pragma unroll
    for (int mt = 0; mt < 4; mt++)
#pragma unroll
        for (int nt = 0; nt < 4; nt++)
#pragma unroll
            for (int e = 0; e < 4; e++) c[mt][nt][e] = 0.f;

    float a_st[4][4];   // 4 A groups per warp (gA = wid*4+i), 4 elems each
    float b_st[8][2];   // 8 B groups per warp (gB = wid*8+i), 2 elems each

    const float* Abase = A + (long)bm * lda;
    const float* Bbase = B + (long)bn * ldb;
    const int nchunk = K >> 5;

    // ---- load chunk c0 into staging regs ----
    auto ldg_chunk = [&](int c0) {
#pragma unroll
        for (int i = 0; i < 4; i++) {
            const int gA = wid * 4 + i;
            const float* ap = Abase + (long)((gA >> 2) * 16 + g) * lda
                              + c0 + (gA & 3) * 8 + tg;
            a_st[i][0] = ap[0];
            a_st[i][1] = ap[8 * lda];
            a_st[i][2] = ap[4];
            a_st[i][3] = ap[8 * lda + 4];
        }
#pragma unroll
        for (int i = 0; i < 8; i++) {
            const int gB = wid * 8 + i;
            const float* bp = Bbase + (long)((gB >> 2) * 8 + g) * ldb
                              + c0 + (gB & 3) * 8 + tg;
            b_st[i][0] = bp[0];
            b_st[i][1] = bp[4];
        }
    };

    // ---- convert staged regs to tf32 hi/lo, store into fragment-layout smem ----
    auto cvt_sts = [&](float* buf) {
        float* Ah = buf;
        float* Al = buf + 4096;
        float* Bh = buf + 8192;
        float* Bl = buf + 12288;
#pragma unroll
        for (int i = 0; i < 4; i++) {
            const int gA = wid * 4 + i;
            float4 h, l;
            h.x = f2tf32(a_st[i][0]); l.x = f2tf32(a_st[i][0] - h.x);
            h.y = f2tf32(a_st[i][1]); l.y = f2tf32(a_st[i][1] - h.y);
            h.z = f2tf32(a_st[i][2]); l.z = f2tf32(a_st[i][2] - h.z);
            h.w = f2tf32(a_st[i][3]); l.w = f2tf32(a_st[i][3] - h.w);
            *(float4*)(Ah + gA * 128 + lane * 4) = h;
            *(float4*)(Al + gA * 128 + lane * 4) = l;
        }
#pragma unroll
        for (int i = 0; i < 8; i++) {
            const int gB = wid * 8 + i;
            float2 h, l;
            h.x = f2tf32(b_st[i][0]); l.x = f2tf32(b_st[i][0] - h.x);
            h.y = f2tf32(b_st[i][1]); l.y = f2tf32(b_st[i][1] - h.y);
            *(float2*)(Bh + gB * 64 + lane * 2) = h;
            *(float2*)(Bl + gB * 64 + lane * 2) = l;
        }
    };

    // ---- MMA over one chunk from smem ----
    auto mma_chunk = [&](const float* buf) {
        const float* Ah = buf;
        const float* Al = buf + 4096;
        const float* Bh = buf + 8192;
        const float* Bl = buf + 12288;
#pragma unroll
        for (int ks = 0; ks < 4; ks++) {
            float4 ah[4];
            float2 bh[4];
#pragma unroll
            for (int mt = 0; mt < 4; mt++)
                ah[mt] = *(const float4*)(Ah + ((wm * 4 + mt) * 4 + ks) * 128 + lane * 4);
#pragma unroll
            for (int nt = 0; nt < 4; nt++)
                bh[nt] = *(const float2*)(Bh + ((wn * 4 + nt) * 4 + ks) * 64 + lane * 2);
#pragma unroll
            for (int mt = 0; mt < 4; mt++)
#pragma unroll
                for (int nt = 0; nt < 4; nt++)
                    mma8(c[mt][nt], ah[mt], bh[nt]);      // hi*hi
            float2 bl[4];
#pragma unroll
            for (int nt = 0; nt < 4; nt++)
                bl[nt] = *(const float2*)(Bl + ((wn * 4 + nt) * 4 + ks) * 64 + lane * 2);
#pragma unroll
            for (int mt = 0; mt < 4; mt++)
#pragma unroll
                for (int nt = 0; nt < 4; nt++)
                    mma8(c[mt][nt], ah[mt], bl[nt]);      // hi*lo
            float4 al[4];
#pragma unroll
            for (int mt = 0; mt < 4; mt++)
                al[mt] = *(const float4*)(Al + ((wm * 4 + mt) * 4 + ks) * 128 + lane * 4);
#pragma unroll
            for (int mt = 0; mt < 4; mt++)
#pragma unroll
                for (int nt = 0; nt < 4; nt++)
                    mma8(c[mt][nt], al[mt], bh[nt]);      // lo*hi
        }
    };

    // ---- pipelined main loop (double-buffered smem) ----
    ldg_chunk(0);
    cvt_sts(sm);
    __syncthreads();
    for (int cc = 0; cc < nchunk; cc++) {
        if (cc + 1 < nchunk) ldg_chunk((cc + 1) << 5);
        mma_chunk(sm + (cc & 1) * 16384);
        if (cc + 1 < nchunk) cvt_sts(sm + ((cc + 1) & 1) * 16384);
        __syncthreads();
    }

    // ---- epilogue ----
    const int bb = bm >> 11;
#pragma unroll
    for (int mt = 0; mt < 4; mt++) {
        const int row = bm + wm * 64 + mt * 16 + g;
#pragma unroll
        for (int nt = 0; nt < 4; nt++) {
            const int col = bn + wn * 32 + nt * 8 + 2 * tg;
            float2 v0 = make_float2(c[mt][nt][0], c[mt][nt][1]);
            float2 v1 = make_float2(c[mt][nt][2], c[mt][nt][3]);
            if (colBias) {
                float2 cb = *(const float2*)(colBias + col);
                v0.x += cb.x; v0.y += cb.y;
                v1.x += cb.x; v1.y += cb.y;
            }
            if (batchBias) {
                float2 pb = *(const float2*)(batchBias + (long)bb * N + col);
                v0.x += pb.x; v0.y += pb.y;
                v1.x += pb.x; v1.y += pb.y;
            }
            float* g0 = C + (long)row * N + col;
            float* g1 = C + (long)(row + 8) * N + col;
            if (ACCUM) {
                float2 o0 = *(const float2*)g0;
                float2 o1 = *(const float2*)g1;
                v0.x += o0.x; v0.y += o0.y;
                v1.x += o1.x; v1.y += o1.y;
            }
            if (RELU) {
                v0.x = fmaxf(v0.x, 0.f); v0.y = fmaxf(v0.y, 0.f);
                v1.x = fmaxf(v1.x, 0.f); v1.y = fmaxf(v1.y, 0.f);
            }
            *(float2*)g0 = v0;
            *(float2*)g1 = v1;
        }
    }
}

// ---------------- flash attention (fp32, 64x64 tiles) ----------------------------
#define SMS 65
__global__ void __launch_bounds__(256) flash_kernel(
    const float* __restrict__ Q, const float* __restrict__ KV, float* __restrict__ O)
{
    extern __shared__ float smf[];
    float* Qs = smf;
    float* Ks = Qs + 64 * SMS;
    float* Vs = Ks + 64 * SMS;
    float* Ps = Vs + 64 * SMS;

    const int tid = threadIdx.x;
    const int bh = blockIdx.y, b = bh >> 4, h = bh & 15;
    const int q0 = blockIdx.x * 64;
    const int r = tid >> 2, c0 = (tid & 3) * 16;

    {
        const float* qg = Q + (long)(b * NB_ + q0 + r) * D_ + h * HD_ + c0;
        float4 t0 = *(const float4*)(qg);
        float4 t1 = *(const float4*)(qg + 4);
        float4 t2 = *(const float4*)(qg + 8);
        float4 t3 = *(const float4*)(qg + 12);
        float* d = Qs + r * SMS + c0;
        d[0] = t0.x; d[1] = t0.y; d[2] = t0.z; d[3] = t0.w;
        d[4] = t1.x; d[5] = t1.y; d[6] = t1.z; d[7] = t1.w;
        d[8] = t2.x; d[9] = t2.y; d[10] = t2.z; d[11] = t2.w;
        d[12] = t3.x; d[13] = t3.y; d[14] = t3.z; d[15] = t3.w;
    }

    const int ty = tid >> 4, tx = tid & 15;
    float m[4], l[4], o[4][4];
#pragma unroll
    for (int i = 0; i < 4; i++) {
        m[i] = -1e30f; l[i] = 0.f;
#pragma unroll
        for (int j = 0; j < 4; j++) o[i][j] = 0.f;
    }

    const float* kg = KV + (long)b * NCTX * 2048 + h * HD_ + c0;

    for (int kt = 0; kt < NCTX; kt += 64) {
        __syncthreads();
        {
            const float* krow = kg + (long)(kt + r) * 2048;
            float4 t0 = *(const float4*)(krow);
            float4 t1 = *(const float4*)(krow + 4);
            float4 t2 = *(const float4*)(krow + 8);
            float4 t3 = *(const float4*)(krow + 12);
            float* d = Ks + r * SMS + c0;
            d[0] = t0.x; d[1] = t0.y; d[2] = t0.z; d[3] = t0.w;
            d[4] = t1.x; d[5] = t1.y; d[6] = t1.z; d[7] = t1.w;
            d[8] = t2.x; d[9] = t2.y; d[10] = t2.z; d[11] = t2.w;
            d[12] = t3.x; d[13] = t3.y; d[14] = t3.z; d[15] = t3.w;
            const float* vrow = krow + 1024;
            t0 = *(const float4*)(vrow);
            t1 = *(const float4*)(vrow + 4);
            t2 = *(const float4*)(vrow + 8);
            t3 = *(const float4*)(vrow + 12);
            d = Vs + r * SMS + c0;
            d[0] = t0.x; d[1] = t0.y; d[2] = t0.z; d[3] = t0.w;
            d[4] = t1.x; d[5] = t1.y; d[6] = t1.z; d[7] = t1.w;
            d[8] = t2.x; d[9] = t2.y; d[10] = t2.z; d[11] = t2.w;
            d[12] = t3.x; d[13] = t3.y; d[14] = t3.z; d[15] = t3.w;
        }
        __syncthreads();

        float S[4][4];
#pragma unroll
        for (int i = 0; i < 4; i++)
#pragma unroll
            for (int j = 0; j < 4; j++) S[i][j] = 0.f;

#pragma unroll 8
        for (int k = 0; k < 64; k++) {
            float qr[4], kr[4];
#pragma unroll
            for (int i = 0; i < 4; i++) qr[i] = Qs[(ty + 16 * i) * SMS + k];
#pragma unroll
            for (int j = 0; j < 4; j++) kr[j] = Ks[(tx + 16 * j) * SMS + k];
#pragma unroll
            for (int i = 0; i < 4; i++)
#pragma unroll
                for (int j = 0; j < 4; j++)
                    S[i][j] += qr[i] * kr[j];
        }

#pragma unroll
        for (int i = 0; i < 4; i++) {
            float mx = -1e30f;
#pragma unroll
            for (int j = 0; j < 4; j++) { S[i][j] *= 0.125f; mx = fmaxf(mx, S[i][j]); }
#pragma unroll
            for (int off = 8; off > 0; off >>= 1)
                mx = fmaxf(mx, __shfl_xor_sync(0xffffffffu, mx, off, 16));
            float mn = fmaxf(m[i], mx);
            float al = expf(m[i] - mn);
            float s = 0.f;
#pragma unroll
            for (int j = 0; j < 4; j++) { S[i][j] = expf(S[i][j] - mn); s += S[i][j]; }
#pragma unroll
            for (int off = 8; off > 0; off >>= 1)
                s += __shfl_xor_sync(0xffffffffu, s, off, 16);
            l[i] = l[i] * al + s;
            m[i] = mn;
#pragma unroll
            for (int j = 0; j < 4; j++) o[i][j] *= al;
        }

#pragma unroll
        for (int i = 0; i < 4; i++)
#pragma unroll
            for (int j = 0; j < 4; j++)
                Ps[(ty + 16 * i) * SMS + tx + 16 * j] = S[i][j];
        __syncthreads();

#pragma unroll 8
        for (int k = 0; k < 64; k++) {
            float pr[4], vr[4];
#pragma unroll
            for (int i = 0; i < 4; i++) pr[i] = Ps[(ty + 16 * i) * SMS + k];
#pragma unroll
            for (int j = 0; j < 4; j++) vr[j] = Vs[k * SMS + tx + 16 * j];
#pragma unroll
            for (int i = 0; i < 4; i++)
#pragma unroll
                for (int j = 0; j < 4; j++)
                    o[i][j] += pr[i] * vr[j];
        }
    }

    float* og = O + (long)(b * NB_ + q0) * D_ + h * HD_;
#pragma unroll
    for (int i = 0; i < 4; i++) {
        float inv = 1.0f / l[i];
#pragma unroll
        for (int j = 0; j < 4; j++)
            og[(long)(ty + 16 * i) * D_ + tx + 16 * j] = o[i][j] * inv;
    }
}

// ---------------- residual + layernorm ------------------------------------------
__global__ void __launch_bounds__(256) ln_kernel(
    const float* __restrict__ X, const float* __restrict__ R,
    const float* __restrict__ gam, const float* __restrict__ bet, float* __restrict__ Y)
{
    __shared__ float red[8];
    const int row = blockIdx.x, tid = threadIdx.x;
    const float* x = X + (long)row * D_;
    const float* rr = R + (long)row * D_;
    float v[4];
    float s = 0.f;
#pragma unroll
    for (int i = 0; i < 4; i++) {
        int c = tid + 256 * i;
        v[i] = x[c] + rr[c];
        s += v[i];
    }
#pragma unroll
    for (int off = 16; off > 0; off >>= 1) s += __shfl_xor_sync(0xffffffffu, s, off);
    if ((tid & 31) == 0) red[tid >> 5] = s;
    __syncthreads();
    float tot = red[0] + red[1] + red[2] + red[3] + red[4] + red[5] + red[6] + red[7];
    float mu = tot * (1.0f / 1024.0f);
    __syncthreads();
    float s2 = 0.f;
#pragma unroll
    for (int i = 0; i < 4; i++) { float d = v[i] - mu; s2 += d * d; }
#pragma unroll
    for (int off = 16; off > 0; off >>= 1) s2 += __shfl_xor_sync(0xffffffffu, s2, off);
    if ((tid & 31) == 0) red[tid >> 5] = s2;
    __syncthreads();
    float tot2 = red[0] + red[1] + red[2] + red[3] + red[4] + red[5] + red[6] + red[7];
    float rstd = rsqrtf(tot2 * (1.0f / 1024.0f) + 1e-5f);
#pragma unroll
    for (int i = 0; i < 4; i++) {
        int c = tid + 256 * i;
        Y[(long)row * D_ + c] = (v[i] - mu) * rstd * gam[c] + bet[c];
    }
}

// ---------------- generic warp-dot: Y[b][j] = act(dot(X[b], W[j]) + b1 + b2) ------
template <int ACT>
__global__ void __launch_bounds__(256) rowdot(
    const float* __restrict__ X, const float* __restrict__ W, int ldw,
    const float* __restrict__ b1, const float* __restrict__ b2,
    float* __restrict__ Y, int Kd, int J)
{
    const int b = blockIdx.x;
    const int w = threadIdx.x >> 5, lane = threadIdx.x & 31;
    const int j = blockIdx.y * 8 + w;
    const float* x = X + (long)b * Kd;
    const float* wr = W + (long)j * ldw;
    float s = 0.f;
    for (int k = lane * 4; k < Kd; k += 128) {
        float4 xv = *(const float4*)(x + k);
        float4 wv = *(const float4*)(wr + k);
        s += xv.x * wv.x + xv.y * wv.y + xv.z * wv.z + xv.w * wv.w;
    }
#pragma unroll
    for (int off = 16; off > 0; off >>= 1) s += __shfl_xor_sync(0xffffffffu, s, off);
    if (lane == 0) {
        if (b1) s += b1[j];
        if (b2) s += b2[j];
        if (ACT == 1) s = s / (1.f + expf(-s));
        Y[(long)b * J + j] = s;
    }
}

// ---------------- small kernels ---------------------------------------------------
__global__ void emb_kernel(const int* __restrict__ t)
{
    const int b = blockIdx.x, i = threadIdx.x;
    float fr = expf(-9.2103403719761836f * (float)i / 511.0f);
    float arg = (float)t[b] * fr;
    g_emb[b * D_ + i] = sinf(arg);
    g_emb[b * D_ + 512 + i] = cosf(arg);
}

__global__ void __launch_bounds__(256) concat_kernel(
    const float* __restrict__ A, const float* __restrict__ C)
{
    const int row = blockIdx.x;
    const int b = row >> 11, j = row & 2047;
    const float* src = (j < 1024) ? (A + ((long)b * 1024 + j) * D_)
                                  : (C + ((long)b * 1024 + (j - 1024)) * D_);
    float4* dst = (float4*)(g_ctxAC + (long)row * D_);
    dst[threadIdx.x] = ((const float4*)src)[threadIdx.x];
}

__global__ void __launch_bounds__(256) router_kernel(
    const float* __restrict__ logits, const int* __restrict__ t,
    float* __restrict__ dispatch, float* __restrict__ combine, float* __restrict__ loadp)
{
    __shared__ float sd[8 * 256];
    const int tid = threadIdx.x;
    const int tok = blockIdx.x * 256 + tid;
    const int b = tok >> 11;
    const float tn = (float)t[b] * 0.001f;
    const float tau_inv = 1.0f / (0.5f + 1.5f * tn);

    float p[8];
    float mx = -1e30f;
#pragma unroll
    for (int e = 0; e < 8; e++) { p[e] = logits[tok * 8 + e] * tau_inv; mx = fmaxf(mx, p[e]); }
    float s = 0.f;
#pragma unroll
    for (int e = 0; e < 8; e++) { p[e] = expf(p[e] - mx); s += p[e]; }
    float inv = 1.0f / s;
#pragma unroll
    for (int e = 0; e < 8; e++) p[e] = 0.85f * (p[e] * inv) + 0.01875f;

    const float w = 0.1f + 0.1f * tn;
    float sh = fmaxf(p[0], w);
    float os = 0.f;
#pragma unroll
    for (int e = 1; e < 8; e++) os += p[e];
    float sc = (1.0f - sh) / fmaxf(os, 1e-8f);
    p[0] = sh;
#pragma unroll
    for (int e = 1; e < 8; e++) p[e] *= sc;

    int i1 = 0; float v1 = p[0];
#pragma unroll
    for (int e = 1; e < 8; e++) if (p[e] > v1) { v1 = p[e]; i1 = e; }
    int i2 = -1; float v2 = -1e30f;
#pragma unroll
    for (int e = 0; e < 8; e++) if (e != i1 && p[e] > v2) { v2 = p[e]; i2 = e; }

    float d[8];
#pragma unroll
    for (int e = 0; e < 8; e++) d[e] = 0.f;
    d[i1] = v1; d[i2] = v2;

    const float cap = 0.5f + 0.1f * tn;
    float ext = 0.f, hs = 0.f;
    float hd[8];
#pragma unroll
    for (int e = 0; e < 8; e++) {
        float ex = fmaxf(d[e] - cap, 0.f);
        d[e] -= ex; ext += ex;
        hd[e] = fmaxf(cap - d[e], 0.f); hs += hd[e];
    }
    hs = fmaxf(hs, 1e-8f);
    float ds = 0.f;
#pragma unroll
    for (int e = 0; e < 8; e++) { d[e] += ext * (hd[e] / hs); ds += d[e]; }
    float ci = 1.0f / (ds + 1e-8f);
#pragma unroll
    for (int e = 0; e < 8; e++) {
        dispatch[tok * 8 + e] = d[e];
        combine[tok * 8 + e] = d[e] * ci;
        sd[e * 256 + tid] = d[e];
    }
    __syncthreads();
    if (tid < 8) {
        float acc = 0.f;
        for (int i = 0; i < 256; i++) acc += sd[tid * 256 + i];
        loadp[blockIdx.x * 8 + tid] = acc;
    }
}

__global__ void penalty_kernel(const float* __restrict__ loadp, float* __restrict__ out)
{
    if (threadIdx.x == 0) {
        const float thr = (2048.0f / 7.0f) * 1.5f;
        float pen = 0.f;
        for (int e = 1; e < 8; e++) {
            float l = 0.f;
            for (int blk = 0; blk < 32; blk++) l += loadp[blk * 8 + e];
            l *= 0.25f;
            float x = l - thr;
            if (x > 0.f) pen += x * x;
        }
        out[0] = 0.01f * pen;
    }
}

// ---------------- launch ----------------------------------------------------------
extern "C" void kernel_launch(void* const* d_in, const int* in_sizes, int n_in,
                              void* d_out, int out_size)
{
    const float* tokens = (const float*)d_in[0];
    const float* outA   = (const float*)d_in[1];
    const float* outC   = (const float*)d_in[2];
    const int*   t      = (const int*)d_in[3];
    const float* in_w   = (const float*)d_in[4];
    const float* in_b   = (const float*)d_in[5];
    const float* op_w   = (const float*)d_in[6];
    const float* op_b   = (const float*)d_in[7];
    const float* lng    = (const float*)d_in[8];
    const float* lnb    = (const float*)d_in[9];
    const float* te_w1  = (const float*)d_in[10];
    const float* te_b1  = (const float*)d_in[11];
    const float* te_w2  = (const float*)d_in[12];
    const float* te_b2  = (const float*)d_in[13];
    const float* gw1    = (const float*)d_in[14];
    const float* gb1    = (const float*)d_in[15];
    const float* gw2    = (const float*)d_in[16];
    const float* gb2    = (const float*)d_in[17];
    const float* ebias  = (const float*)d_in[18];
    float* out = (float*)d_out;

    float *p_ctxAC, *p_q, *p_kv, *p_attn, *p_proj, *p_ctxB, *p_hidden,
          *p_logits, *p_emb, *p_h2, *p_temb, *p_tec, *p_loadp;
    cudaGetSymbolAddress((void**)&p_ctxAC, g_ctxAC);
    cudaGetSymbolAddress((void**)&p_q, g_q);
    cudaGetSymbolAddress((void**)&p_kv, g_kv);
    cudaGetSymbolAddress((void**)&p_attn, g_attn);
    cudaGetSymbolAddress((void**)&p_proj, g_proj);
    cudaGetSymbolAddress((void**)&p_ctxB, g_ctxB);
    cudaGetSymbolAddress((void**)&p_hidden, g_hidden);
    cudaGetSymbolAddress((void**)&p_logits, g_logits);
    cudaGetSymbolAddress((void**)&p_emb, g_emb);
    cudaGetSymbolAddress((void**)&p_h2, g_h2);
    cudaGetSymbolAddress((void**)&p_temb, g_temb);
    cudaGetSymbolAddress((void**)&p_tec, g_tec);
    cudaGetSymbolAddress((void**)&p_loadp, g_loadp);

    cudaFuncSetAttribute(flash_kernel, cudaFuncAttributeMaxDynamicSharedMemorySize,
                         4 * 64 * SMS * (int)sizeof(float));
    cudaFuncSetAttribute(tgemm_nt<false, false>,
                         cudaFuncAttributeMaxDynamicSharedMemorySize, TGEMM_SMEM);
    cudaFuncSetAttribute(tgemm_nt<true, true>,
                         cudaFuncAttributeMaxDynamicSharedMemorySize, TGEMM_SMEM);

    // ---- time embedding chain ----
    emb_kernel<<<BATCH, 512>>>(t);
    rowdot<1><<<dim3(BATCH, 256), 256>>>(p_emb, te_w1, 1024, te_b1, nullptr, p_h2, 1024, 2048);
    rowdot<0><<<dim3(BATCH, 128), 256>>>(p_h2, te_w2, 2048, te_b2, nullptr, p_temb, 2048, 1024);
    rowdot<0><<<dim3(BATCH, 128), 256>>>(p_temb, gw1 + 2048, 3072, gb1, nullptr, p_tec, 1024, 1024);

    // ---- attention path ----
    concat_kernel<<<NTOK, 256>>>(outA, outC);
    tgemm_nt<false, false><<<dim3(8, 64), 256, TGEMM_SMEM>>>(
        1024, 1024, tokens, 1024, in_w, 1024, p_q, in_b, nullptr);
    tgemm_nt<false, false><<<dim3(16, 64), 256, TGEMM_SMEM>>>(
        2048, 1024, p_ctxAC, 1024, in_w + 1024 * 1024, 1024, p_kv, in_b + 1024, nullptr);
    flash_kernel<<<dim3(32, BATCH * H_), 256, 4 * 64 * SMS * sizeof(float)>>>(p_q, p_kv, p_attn);
    tgemm_nt<false, false><<<dim3(8, 64), 256, TGEMM_SMEM>>>(
        1024, 1024, p_attn, 1024, op_w, 1024, p_proj, op_b, nullptr);
    ln_kernel<<<NTOK, 256>>>(p_proj, tokens, lng, lnb, p_ctxB);

    // ---- gate hidden ----
    tgemm_nt<false, false><<<dim3(8, 64), 256, TGEMM_SMEM>>>(
        1024, 1024, tokens, 1024, gw1, 3072, p_hidden, nullptr, p_tec);
    tgemm_nt<true, true><<<dim3(8, 64), 256, TGEMM_SMEM>>>(
        1024, 1024, p_ctxB, 1024, gw1 + 1024, 3072, p_hidden, nullptr, nullptr);

    // ---- logits + routing ----
    rowdot<0><<<dim3(NTOK, 1), 256>>>(p_hidden, gw2, 1024, gb2, ebias, p_logits, 1024, 8);
    router_kernel<<<32, 256>>>(p_logits, t, out, out + 65536, p_loadp);
    penalty_kernel<<<1, 32>>>(p_loadp, out + 2 * 65536);
}

// round 4
// speedup vs baseline: 1.1479x; 1.0002x over previous
#include <cuda_runtime.h>
#include <math.h>
#include <stdint.h>

#define D_    1024
#define BATCH 4
#define NB_   2048
#define NCTX  2048
#define H_    16
#define HD_   64
#define E_    8
#define NTOK  8192

// ---------------- scratch (device globals; no allocation allowed) ----------------
__device__ float g_ctxAC[NTOK * D_];
__device__ float g_q[NTOK * D_];
__device__ float g_kv[NTOK * 2 * D_];
__device__ float g_attn[NTOK * D_];
__device__ float g_proj[NTOK * D_];
__device__ float g_ctxB[NTOK * D_];
__device__ float g_hidden[NTOK * D_];
__device__ float g_logits[NTOK * E_];
__device__ float g_emb[BATCH * D_];
__device__ float g_h2[BATCH * 2 * D_];
__device__ float g_temb[BATCH * D_];
__device__ float g_tec[BATCH * D_];
__device__ float g_loadp[32 * E_];

// ================= tf32 helpers ==================================================
__device__ __forceinline__ float f2tf32(float x) {
    uint32_t r;
    asm("cvt.rna.tf32.f32 %0, %1;" : "=r"(r) : "f"(x));
    return __uint_as_float(r);
}
__device__ __forceinline__ void mma8(float* d, const float4 a, const float2 b) {
    asm volatile(
        "mma.sync.aligned.m16n8k8.row.col.f32.tf32.tf32.f32 "
        "{%0,%1,%2,%3}, {%4,%5,%6,%7}, {%8,%9}, {%0,%1,%2,%3};\n"
        : "+f"(d[0]), "+f"(d[1]), "+f"(d[2]), "+f"(d[3])
        : "r"(__float_as_uint(a.x)), "r"(__float_as_uint(a.y)),
          "r"(__float_as_uint(a.z)), "r"(__float_as_uint(a.w)),
          "r"(__float_as_uint(b.x)), "r"(__float_as_uint(b.y)));
}

// Buffer layout (floats): Ah[4096] Al[4096] Bh[4096] Bl[4096] ; two buffers.
#define TGEMM_SMEM (2 * 16384 * 4)

// ============= 3xTF32 mma.sync GEMM: C(MxN) = A(MxK)*B(NxK)^T + epilogue =========
// grid=(N/128, M/128), 256 threads, 8 warps (2M x 4N), warp tile 64x32, K%32==0.
// A/B staged in registers, converted to tf32 hi/lo, stored to smem in exact
// m16n8k8 fragment layout (LDS.128 / LDS.64 conflict-free reads).
template <bool ACCUM, bool RELU>
__global__ void __launch_bounds__(256) tgemm_nt(
    int N, int K,
    const float* __restrict__ A, int lda,
    const float* __restrict__ B, int ldb,
    float* __restrict__ C,
    const float* __restrict__ colBias,
    const float* __restrict__ batchBias)
{
    extern __shared__ float sm[];
    const int tid = threadIdx.x, wid = tid >> 5, lane = tid & 31;
    const int g = lane >> 2, tg = lane & 3;
    const int bm = blockIdx.y * 128, bn = blockIdx.x * 128;
    const int wm = wid & 1, wn = wid >> 1;

    float c[4][4][4];
#pragma unroll
    for (int mt = 0; mt < 4; mt++)
#pragma unroll
        for (int nt = 0; nt < 4; nt++)
#pragma unroll
            for (int e = 0; e < 4; e++) c[mt][nt][e] = 0.f;

    float a_st[4][4];   // 4 A groups per warp (gA = wid*4+i), 4 elems each
    float b_st[8][2];   // 8 B groups per warp (gB = wid*8+i), 2 elems each

    const float* Abase = A + (long)bm * lda;
    const float* Bbase = B + (long)bn * ldb;
    const int nchunk = K >> 5;

    // ---- load chunk c0 into staging regs ----
    auto ldg_chunk = [&](int c0) {
#pragma unroll
        for (int i = 0; i < 4; i++) {
            const int gA = wid * 4 + i;
            const float* ap = Abase + (long)((gA >> 2) * 16 + g) * lda
                              + c0 + (gA & 3) * 8 + tg;
            a_st[i][0] = ap[0];
            a_st[i][1] = ap[8 * lda];
            a_st[i][2] = ap[4];
            a_st[i][3] = ap[8 * lda + 4];
        }
#pragma unroll
        for (int i = 0; i < 8; i++) {
            const int gB = wid * 8 + i;
            const float* bp = Bbase + (long)((gB >> 2) * 8 + g) * ldb
                              + c0 + (gB & 3) * 8 + tg;
            b_st[i][0] = bp[0];
            b_st[i][1] = bp[4];
        }
    };

    // ---- convert staged regs to tf32 hi/lo, store into fragment-layout smem ----
    auto cvt_sts = [&](float* buf) {
        float* Ah = buf;
        float* Al = buf + 4096;
        float* Bh = buf + 8192;
        float* Bl = buf + 12288;
#pragma unroll
        for (int i = 0; i < 4; i++) {
            const int gA = wid * 4 + i;
            float4 h, l;
            h.x = f2tf32(a_st[i][0]); l.x = f2tf32(a_st[i][0] - h.x);
            h.y = f2tf32(a_st[i][1]); l.y = f2tf32(a_st[i][1] - h.y);
            h.z = f2tf32(a_st[i][2]); l.z = f2tf32(a_st[i][2] - h.z);
            h.w = f2tf32(a_st[i][3]); l.w = f2tf32(a_st[i][3] - h.w);
            *(float4*)(Ah + gA * 128 + lane * 4) = h;
            *(float4*)(Al + gA * 128 + lane * 4) = l;
        }
#pragma unroll
        for (int i = 0; i < 8; i++) {
            const int gB = wid * 8 + i;
            float2 h, l;
            h.x = f2tf32(b_st[i][0]); l.x = f2tf32(b_st[i][0] - h.x);
            h.y = f2tf32(b_st[i][1]); l.y = f2tf32(b_st[i][1] - h.y);
            *(float2*)(Bh + gB * 64 + lane * 2) = h;
            *(float2*)(Bl + gB * 64 + lane * 2) = l;
        }
    };

    // ---- MMA over one chunk from smem ----
    auto mma_chunk = [&](const float* buf) {
        const float* Ah = buf;
        const float* Al = buf + 4096;
        const float* Bh = buf + 8192;
        const float* Bl = buf + 12288;
#pragma unroll
        for (int ks = 0; ks < 4; ks++) {
            float4 ah[4];
            float2 bh[4];
#pragma unroll
            for (int mt = 0; mt < 4; mt++)
                ah[mt] = *(const float4*)(Ah + ((wm * 4 + mt) * 4 + ks) * 128 + lane * 4);
#pragma unroll
            for (int nt = 0; nt < 4; nt++)
                bh[nt] = *(const float2*)(Bh + ((wn * 4 + nt) * 4 + ks) * 64 + lane * 2);
#pragma unroll
            for (int mt = 0; mt < 4; mt++)
#pragma unroll
                for (int nt = 0; nt < 4; nt++)
                    mma8(c[mt][nt], ah[mt], bh[nt]);      // hi*hi
            float2 bl[4];
#pragma unroll
            for (int nt = 0; nt < 4; nt++)
                bl[nt] = *(const float2*)(Bl + ((wn * 4 + nt) * 4 + ks) * 64 + lane * 2);
#pragma unroll
            for (int mt = 0; mt < 4; mt++)
#pragma unroll
                for (int nt = 0; nt < 4; nt++)
                    mma8(c[mt][nt], ah[mt], bl[nt]);      // hi*lo
            float4 al[4];
#pragma unroll
            for (int mt = 0; mt < 4; mt++)
                al[mt] = *(const float4*)(Al + ((wm * 4 + mt) * 4 + ks) * 128 + lane * 4);
#pragma unroll
            for (int mt = 0; mt < 4; mt++)
#pragma unroll
                for (int nt = 0; nt < 4; nt++)
                    mma8(c[mt][nt], al[mt], bh[nt]);      // lo*hi
        }
    };

    // ---- pipelined main loop (double-buffered smem) ----
    ldg_chunk(0);
    cvt_sts(sm);
    __syncthreads();
    for (int cc = 0; cc < nchunk; cc++) {
        if (cc + 1 < nchunk) ldg_chunk((cc + 1) << 5);
        mma_chunk(sm + (cc & 1) * 16384);
        if (cc + 1 < nchunk) cvt_sts(sm + ((cc + 1) & 1) * 16384);
        __syncthreads();
    }

    // ---- epilogue ----
    const int bb = bm >> 11;
#pragma unroll
    for (int mt = 0; mt < 4; mt++) {
        const int row = bm + wm * 64 + mt * 16 + g;
#pragma unroll
        for (int nt = 0; nt < 4; nt++) {
            const int col = bn + wn * 32 + nt * 8 + 2 * tg;
            float2 v0 = make_float2(c[mt][nt][0], c[mt][nt][1]);
            float2 v1 = make_float2(c[mt][nt][2], c[mt][nt][3]);
            if (colBias) {
                float2 cb = *(const float2*)(colBias + col);
                v0.x += cb.x; v0.y += cb.y;
                v1.x += cb.x; v1.y += cb.y;
            }
            if (batchBias) {
                float2 pb = *(const float2*)(batchBias + (long)bb * N + col);
                v0.x += pb.x; v0.y += pb.y;
                v1.x += pb.x; v1.y += pb.y;
            }
            float* g0 = C + (long)row * N + col;
            float* g1 = C + (long)(row + 8) * N + col;
            if (ACCUM) {
                float2 o0 = *(const float2*)g0;
                float2 o1 = *(const float2*)g1;
                v0.x += o0.x; v0.y += o0.y;
                v1.x += o1.x; v1.y += o1.y;
            }
            if (RELU) {
                v0.x = fmaxf(v0.x, 0.f); v0.y = fmaxf(v0.y, 0.f);
                v1.x = fmaxf(v1.x, 0.f); v1.y = fmaxf(v1.y, 0.f);
            }
            *(float2*)g0 = v0;
            *(float2*)g1 = v1;
        }
    }
}

// ---------------- flash attention (fp32, 64x64 tiles) ----------------------------
#define SMS 65
__global__ void __launch_bounds__(256) flash_kernel(
    const float* __restrict__ Q, const float* __restrict__ KV, float* __restrict__ O)
{
    extern __shared__ float smf[];
    float* Qs = smf;
    float* Ks = Qs + 64 * SMS;
    float* Vs = Ks + 64 * SMS;
    float* Ps = Vs + 64 * SMS;

    const int tid = threadIdx.x;
    const int bh = blockIdx.y, b = bh >> 4, h = bh & 15;
    const int q0 = blockIdx.x * 64;
    const int r = tid >> 2, c0 = (tid & 3) * 16;

    {
        const float* qg = Q + (long)(b * NB_ + q0 + r) * D_ + h * HD_ + c0;
        float4 t0 = *(const float4*)(qg);
        float4 t1 = *(const float4*)(qg + 4);
        float4 t2 = *(const float4*)(qg + 8);
        float4 t3 = *(const float4*)(qg + 12);
        float* d = Qs + r * SMS + c0;
        d[0] = t0.x; d[1] = t0.y; d[2] = t0.z; d[3] = t0.w;
        d[4] = t1.x; d[5] = t1.y; d[6] = t1.z; d[7] = t1.w;
        d[8] = t2.x; d[9] = t2.y; d[10] = t2.z; d[11] = t2.w;
        d[12] = t3.x; d[13] = t3.y; d[14] = t3.z; d[15] = t3.w;
    }

    const int ty = tid >> 4, tx = tid & 15;
    float m[4], l[4], o[4][4];
#pragma unroll
    for (int i = 0; i < 4; i++) {
        m[i] = -1e30f; l[i] = 0.f;
#pragma unroll
        for (int j = 0; j < 4; j++) o[i][j] = 0.f;
    }

    const float* kg = KV + (long)b * NCTX * 2048 + h * HD_ + c0;

    for (int kt = 0; kt < NCTX; kt += 64) {
        __syncthreads();
        {
            const float* krow = kg + (long)(kt + r) * 2048;
            float4 t0 = *(const float4*)(krow);
            float4 t1 = *(const float4*)(krow + 4);
            float4 t2 = *(const float4*)(krow + 8);
            float4 t3 = *(const float4*)(krow + 12);
            float* d = Ks + r * SMS + c0;
            d[0] = t0.x; d[1] = t0.y; d[2] = t0.z; d[3] = t0.w;
            d[4] = t1.x; d[5] = t1.y; d[6] = t1.z; d[7] = t1.w;
            d[8] = t2.x; d[9] = t2.y; d[10] = t2.z; d[11] = t2.w;
            d[12] = t3.x; d[13] = t3.y; d[14] = t3.z; d[15] = t3.w;
            const float* vrow = krow + 1024;
            t0 = *(const float4*)(vrow);
            t1 = *(const float4*)(vrow + 4);
            t2 = *(const float4*)(vrow + 8);
            t3 = *(const float4*)(vrow + 12);
            d = Vs + r * SMS + c0;
            d[0] = t0.x; d[1] = t0.y; d[2] = t0.z; d[3] = t0.w;
            d[4] = t1.x; d[5] = t1.y; d[6] = t1.z; d[7] = t1.w;
            d[8] = t2.x; d[9] = t2.y; d[10] = t2.z; d[11] = t2.w;
            d[12] = t3.x; d[13] = t3.y; d[14] = t3.z; d[15] = t3.w;
        }
        __syncthreads();

        float S[4][4];
#pragma unroll
        for (int i = 0; i < 4; i++)
#pragma unroll
            for (int j = 0; j < 4; j++) S[i][j] = 0.f;

#pragma unroll 8
        for (int k = 0; k < 64; k++) {
            float qr[4], kr[4];
#pragma unroll
            for (int i = 0; i < 4; i++) qr[i] = Qs[(ty + 16 * i) * SMS + k];
#pragma unroll
            for (int j = 0; j < 4; j++) kr[j] = Ks[(tx + 16 * j) * SMS + k];
#pragma unroll
            for (int i = 0; i < 4; i++)
#pragma unroll
                for (int j = 0; j < 4; j++)
                    S[i][j] += qr[i] * kr[j];
        }

#pragma unroll
        for (int i = 0; i < 4; i++) {
            float mx = -1e30f;
#pragma unroll
            for (int j = 0; j < 4; j++) { S[i][j] *= 0.125f; mx = fmaxf(mx, S[i][j]); }
#pragma unroll
            for (int off = 8; off > 0; off >>= 1)
                mx = fmaxf(mx, __shfl_xor_sync(0xffffffffu, mx, off, 16));
            float mn = fmaxf(m[i], mx);
            float al = expf(m[i] - mn);
            float s = 0.f;
#pragma unroll
            for (int j = 0; j < 4; j++) { S[i][j] = expf(S[i][j] - mn); s += S[i][j]; }
#pragma unroll
            for (int off = 8; off > 0; off >>= 1)
                s += __shfl_xor_sync(0xffffffffu, s, off, 16);
            l[i] = l[i] * al + s;
            m[i] = mn;
#pragma unroll
            for (int j = 0; j < 4; j++) o[i][j] *= al;
        }

#pragma unroll
        for (int i = 0; i < 4; i++)
#pragma unroll
            for (int j = 0; j < 4; j++)
                Ps[(ty + 16 * i) * SMS + tx + 16 * j] = S[i][j];
        __syncthreads();

#pragma unroll 8
        for (int k = 0; k < 64; k++) {
            float pr[4], vr[4];
#pragma unroll
            for (int i = 0; i < 4; i++) pr[i] = Ps[(ty + 16 * i) * SMS + k];
#pragma unroll
            for (int j = 0; j < 4; j++) vr[j] = Vs[k * SMS + tx + 16 * j];
#pragma unroll
            for (int i = 0; i < 4; i++)
#pragma unroll
                for (int j = 0; j < 4; j++)
                    o[i][j] += pr[i] * vr[j];
        }
    }

    float* og = O + (long)(b * NB_ + q0) * D_ + h * HD_;
#pragma unroll
    for (int i = 0; i < 4; i++) {
        float inv = 1.0f / l[i];
#pragma unroll
        for (int j = 0; j < 4; j++)
            og[(long)(ty + 16 * i) * D_ + tx + 16 * j] = o[i][j] * inv;
    }
}

// ---------------- residual + layernorm ------------------------------------------
__global__ void __launch_bounds__(256) ln_kernel(
    const float* __restrict__ X, const float* __restrict__ R,
    const float* __restrict__ gam, const float* __restrict__ bet, float* __restrict__ Y)
{
    __shared__ float red[8];
    const int row = blockIdx.x, tid = threadIdx.x;
    const float* x = X + (long)row * D_;
    const float* rr = R + (long)row * D_;
    float v[4];
    float s = 0.f;
#pragma unroll
    for (int i = 0; i < 4; i++) {
        int c = tid + 256 * i;
        v[i] = x[c] + rr[c];
        s += v[i];
    }
#pragma unroll
    for (int off = 16; off > 0; off >>= 1) s += __shfl_xor_sync(0xffffffffu, s, off);
    if ((tid & 31) == 0) red[tid >> 5] = s;
    __syncthreads();
    float tot = red[0] + red[1] + red[2] + red[3] + red[4] + red[5] + red[6] + red[7];
    float mu = tot * (1.0f / 1024.0f);
    __syncthreads();
    float s2 = 0.f;
#pragma unroll
    for (int i = 0; i < 4; i++) { float d = v[i] - mu; s2 += d * d; }
#pragma unroll
    for (int off = 16; off > 0; off >>= 1) s2 += __shfl_xor_sync(0xffffffffu, s2, off);
    if ((tid & 31) == 0) red[tid >> 5] = s2;
    __syncthreads();
    float tot2 = red[0] + red[1] + red[2] + red[3] + red[4] + red[5] + red[6] + red[7];
    float rstd = rsqrtf(tot2 * (1.0f / 1024.0f) + 1e-5f);
#pragma unroll
    for (int i = 0; i < 4; i++) {
        int c = tid + 256 * i;
        Y[(long)row * D_ + c] = (v[i] - mu) * rstd * gam[c] + bet[c];
    }
}

// ---------------- generic warp-dot: Y[b][j] = act(dot(X[b], W[j]) + b1 + b2) ------
template <int ACT>
__global__ void __launch_bounds__(256) rowdot(
    const float* __restrict__ X, const float* __restrict__ W, int ldw,
    const float* __restrict__ b1, const float* __restrict__ b2,
    float* __restrict__ Y, int Kd, int J)
{
    const int b = blockIdx.x;
    const int w = threadIdx.x >> 5, lane = threadIdx.x & 31;
    const int j = blockIdx.y * 8 + w;
    const float* x = X + (long)b * Kd;
    const float* wr = W + (long)j * ldw;
    float s = 0.f;
    for (int k = lane * 4; k < Kd; k += 128) {
        float4 xv = *(const float4*)(x + k);
        float4 wv = *(const float4*)(wr + k);
        s += xv.x * wv.x + xv.y * wv.y + xv.z * wv.z + xv.w * wv.w;
    }
#pragma unroll
    for (int off = 16; off > 0; off >>= 1) s += __shfl_xor_sync(0xffffffffu, s, off);
    if (lane == 0) {
        if (b1) s += b1[j];
        if (b2) s += b2[j];
        if (ACT == 1) s = s / (1.f + expf(-s));
        Y[(long)b * J + j] = s;
    }
}

// ---------------- small kernels ---------------------------------------------------
__global__ void emb_kernel(const int* __restrict__ t)
{
    const int b = blockIdx.x, i = threadIdx.x;
    float fr = expf(-9.2103403719761836f * (float)i / 511.0f);
    float arg = (float)t[b] * fr;
    g_emb[b * D_ + i] = sinf(arg);
    g_emb[b * D_ + 512 + i] = cosf(arg);
}

__global__ void __launch_bounds__(256) concat_kernel(
    const float* __restrict__ A, const float* __restrict__ C)
{
    const int row = blockIdx.x;
    const int b = row >> 11, j = row & 2047;
    const float* src = (j < 1024) ? (A + ((long)b * 1024 + j) * D_)
                                  : (C + ((long)b * 1024 + (j - 1024)) * D_);
    float4* dst = (float4*)(g_ctxAC + (long)row * D_);
    dst[threadIdx.x] = ((const float4*)src)[threadIdx.x];
}

__global__ void __launch_bounds__(256) router_kernel(
    const float* __restrict__ logits, const int* __restrict__ t,
    float* __restrict__ dispatch, float* __restrict__ combine, float* __restrict__ loadp)
{
    __shared__ float sd[8 * 256];
    const int tid = threadIdx.x;
    const int tok = blockIdx.x * 256 + tid;
    const int b = tok >> 11;
    const float tn = (float)t[b] * 0.001f;
    const float tau_inv = 1.0f / (0.5f + 1.5f * tn);

    float p[8];
    float mx = -1e30f;
#pragma unroll
    for (int e = 0; e < 8; e++) { p[e] = logits[tok * 8 + e] * tau_inv; mx = fmaxf(mx, p[e]); }
    float s = 0.f;
#pragma unroll
    for (int e = 0; e < 8; e++) { p[e] = expf(p[e] - mx); s += p[e]; }
    float inv = 1.0f / s;
#pragma unroll
    for (int e = 0; e < 8; e++) p[e] = 0.85f * (p[e] * inv) + 0.01875f;

    const float w = 0.1f + 0.1f * tn;
    float sh = fmaxf(p[0], w);
    float os = 0.f;
#pragma unroll
    for (int e = 1; e < 8; e++) os += p[e];
    float sc = (1.0f - sh) / fmaxf(os, 1e-8f);
    p[0] = sh;
#pragma unroll
    for (int e = 1; e < 8; e++) p[e] *= sc;

    int i1 = 0; float v1 = p[0];
#pragma unroll
    for (int e = 1; e < 8; e++) if (p[e] > v1) { v1 = p[e]; i1 = e; }
    int i2 = -1; float v2 = -1e30f;
#pragma unroll
    for (int e = 0; e < 8; e++) if (e != i1 && p[e] > v2) { v2 = p[e]; i2 = e; }

    float d[8];
#pragma unroll
    for (int e = 0; e < 8; e++) d[e] = 0.f;
    d[i1] = v1; d[i2] = v2;

    const float cap = 0.5f + 0.1f * tn;
    float ext = 0.f, hs = 0.f;
    float hd[8];
#pragma unroll
    for (int e = 0; e < 8; e++) {
        float ex = fmaxf(d[e] - cap, 0.f);
        d[e] -= ex; ext += ex;
        hd[e] = fmaxf(cap - d[e], 0.f); hs += hd[e];
    }
    hs = fmaxf(hs, 1e-8f);
    float ds = 0.f;
#pragma unroll
    for (int e = 0; e < 8; e++) { d[e] += ext * (hd[e] / hs); ds += d[e]; }
    float ci = 1.0f / (ds + 1e-8f);
#pragma unroll
    for (int e = 0; e < 8; e++) {
        dispatch[tok * 8 + e] = d[e];
        combine[tok * 8 + e] = d[e] * ci;
        sd[e * 256 + tid] = d[e];
    }
    __syncthreads();
    if (tid < 8) {
        float acc = 0.f;
        for (int i = 0; i < 256; i++) acc += sd[tid * 256 + i];
        loadp[blockIdx.x * 8 + tid] = acc;
    }
}

__global__ void penalty_kernel(const float* __restrict__ loadp, float* __restrict__ out)
{
    if (threadIdx.x == 0) {
        const float thr = (2048.0f / 7.0f) * 1.5f;
        float pen = 0.f;
        for (int e = 1; e < 8; e++) {
            float l = 0.f;
            for (int blk = 0; blk < 32; blk++) l += loadp[blk * 8 + e];
            l *= 0.25f;
            float x = l - thr;
            if (x > 0.f) pen += x * x;
        }
        out[0] = 0.01f * pen;
    }
}

// ---------------- launch ----------------------------------------------------------
extern "C" void kernel_launch(void* const* d_in, const int* in_sizes, int n_in,
                              void* d_out, int out_size)
{
    const float* tokens = (const float*)d_in[0];
    const float* outA   = (const float*)d_in[1];
    const float* outC   = (const float*)d_in[2];
    const int*   t      = (const int*)d_in[3];
    const float* in_w   = (const float*)d_in[4];
    const float* in_b   = (const float*)d_in[5];
    const float* op_w   = (const float*)d_in[6];
    const float* op_b   = (const float*)d_in[7];
    const float* lng    = (const float*)d_in[8];
    const float* lnb    = (const float*)d_in[9];
    const float* te_w1  = (const float*)d_in[10];
    const float* te_b1  = (const float*)d_in[11];
    const float* te_w2  = (const float*)d_in[12];
    const float* te_b2  = (const float*)d_in[13];
    const float* gw1    = (const float*)d_in[14];
    const float* gb1    = (const float*)d_in[15];
    const float* gw2    = (const float*)d_in[16];
    const float* gb2    = (const float*)d_in[17];
    const float* ebias  = (const float*)d_in[18];
    float* out = (float*)d_out;

    float *p_ctxAC, *p_q, *p_kv, *p_attn, *p_proj, *p_ctxB, *p_hidden,
          *p_logits, *p_emb, *p_h2, *p_temb, *p_tec, *p_loadp;
    cudaGetSymbolAddress((void**)&p_ctxAC, g_ctxAC);
    cudaGetSymbolAddress((void**)&p_q, g_q);
    cudaGetSymbolAddress((void**)&p_kv, g_kv);
    cudaGetSymbolAddress((void**)&p_attn, g_attn);
    cudaGetSymbolAddress((void**)&p_proj, g_proj);
    cudaGetSymbolAddress((void**)&p_ctxB, g_ctxB);
    cudaGetSymbolAddress((void**)&p_hidden, g_hidden);
    cudaGetSymbolAddress((void**)&p_logits, g_logits);
    cudaGetSymbolAddress((void**)&p_emb, g_emb);
    cudaGetSymbolAddress((void**)&p_h2, g_h2);
    cudaGetSymbolAddress((void**)&p_temb, g_temb);
    cudaGetSymbolAddress((void**)&p_tec, g_tec);
    cudaGetSymbolAddress((void**)&p_loadp, g_loadp);

    cudaFuncSetAttribute(flash_kernel, cudaFuncAttributeMaxDynamicSharedMemorySize,
                         4 * 64 * SMS * (int)sizeof(float));
    cudaFuncSetAttribute(tgemm_nt<false, false>,
                         cudaFuncAttributeMaxDynamicSharedMemorySize, TGEMM_SMEM);
    cudaFuncSetAttribute(tgemm_nt<true, true>,
                         cudaFuncAttributeMaxDynamicSharedMemorySize, TGEMM_SMEM);

    // ---- time embedding chain ----
    emb_kernel<<<BATCH, 512>>>(t);
    rowdot<1><<<dim3(BATCH, 256), 256>>>(p_emb, te_w1, 1024, te_b1, nullptr, p_h2, 1024, 2048);
    rowdot<0><<<dim3(BATCH, 128), 256>>>(p_h2, te_w2, 2048, te_b2, nullptr, p_temb, 2048, 1024);
    rowdot<0><<<dim3(BATCH, 128), 256>>>(p_temb, gw1 + 2048, 3072, gb1, nullptr, p_tec, 1024, 1024);

    // ---- attention path ----
    concat_kernel<<<NTOK, 256>>>(outA, outC);
    tgemm_nt<false, false><<<dim3(8, 64), 256, TGEMM_SMEM>>>(
        1024, 1024, tokens, 1024, in_w, 1024, p_q, in_b, nullptr);
    tgemm_nt<false, false><<<dim3(16, 64), 256, TGEMM_SMEM>>>(
        2048, 1024, p_ctxAC, 1024, in_w + 1024 * 1024, 1024, p_kv, in_b + 1024, nullptr);
    flash_kernel<<<dim3(32, BATCH * H_), 256, 4 * 64 * SMS * sizeof(float)>>>(p_q, p_kv, p_attn);
    tgemm_nt<false, false><<<dim3(8, 64), 256, TGEMM_SMEM>>>(
        1024, 1024, p_attn, 1024, op_w, 1024, p_proj, op_b, nullptr);
    ln_kernel<<<NTOK, 256>>>(p_proj, tokens, lng, lnb, p_ctxB);

    // ---- gate hidden ----
    tgemm_nt<false, false><<<dim3(8, 64), 256, TGEMM_SMEM>>>(
        1024, 1024, tokens, 1024, gw1, 3072, p_hidden, nullptr, p_tec);
    tgemm_nt<true, true><<<dim3(8, 64), 256, TGEMM_SMEM>>>(
        1024, 1024, p_ctxB, 1024, gw1 + 1024, 3072, p_hidden, nullptr, nullptr);

    // ---- logits + routing ----
    rowdot<0><<<dim3(NTOK, 1), 256>>>(p_hidden, gw2, 1024, gb2, ebias, p_logits, 1024, 8);
    router_kernel<<<32, 256>>>(p_logits, t, out, out + 65536, p_loadp);
    penalty_kernel<<<1, 32>>>(p_loadp, out + 2 * 65536);
}

// round 5
// speedup vs baseline: 2.6191x; 2.2817x over previous
#include <cuda_runtime.h>
#include <cuda_fp16.h>
#include <math.h>
#include <stdint.h>

#define D_    1024
#define BATCH 4
#define NB_   2048
#define NCTX  2048
#define H_    16
#define HD_   64
#define E_    8
#define NTOK  8192

// ---------------- scratch (device globals; no allocation allowed) ----------------
__device__ float g_ctxAC[NTOK * D_];
__device__ float g_q[NTOK * D_];
__device__ float g_kv[NTOK * 2 * D_];
__device__ float g_attn[NTOK * D_];
__device__ float g_proj[NTOK * D_];
__device__ float g_ctxB[NTOK * D_];
__device__ float g_hidden[NTOK * D_];
__device__ float g_logits[NTOK * E_];
__device__ float g_emb[BATCH * D_];
__device__ float g_h2[BATCH * 2 * D_];
__device__ float g_temb[BATCH * D_];
__device__ float g_tec[BATCH * D_];
__device__ float g_loadp[32 * E_];

// ================= fp16 split helpers ============================================
__device__ __forceinline__ void split_pair(float x, float y, uint32_t& hw, uint32_t& lw)
{
    __half2 h = __floats2half2_rn(x, y);
    hw = *reinterpret_cast<uint32_t*>(&h);
    float rx = x - __low2float(h);
    float ry = y - __high2float(h);
    __half2 l = __floats2half2_rn(rx, ry);
    lw = *reinterpret_cast<uint32_t*>(&l);
}
__device__ __forceinline__ void mma16(float* c, uint32_t a0, uint32_t a1, uint32_t a2,
                                      uint32_t a3, uint32_t b0, uint32_t b1)
{
    asm volatile(
        "mma.sync.aligned.m16n8k16.row.col.f32.f16.f16.f32 "
        "{%0,%1,%2,%3},{%4,%5,%6,%7},{%8,%9},{%0,%1,%2,%3};\n"
        : "+f"(c[0]), "+f"(c[1]), "+f"(c[2]), "+f"(c[3])
        : "r"(a0), "r"(a1), "r"(a2), "r"(a3), "r"(b0), "r"(b1));
}

// Buffer (uint32 words): Ah[2048] Al[2048] Bh[1024] Bl[1024] = 6144 words; x2 buffers
#define HGEMM_SMEM (2 * 6144 * 4)

// ============= 3xFP16 mma GEMM: C(MxN) = A(MxK)*B(NxK)^T + epilogue ==============
// grid=(N/64, M/128), 128 threads, 4 warps (2M x 2N), warp tile 64x32, K%32==0.
template <bool ACCUM, bool RELU>
__global__ void __launch_bounds__(128, 3) hgemm_nt(
    int N, int K,
    const float* __restrict__ A, int lda,
    const float* __restrict__ B, int ldb,
    float* __restrict__ C,
    const float* __restrict__ colBias,
    const float* __restrict__ batchBias)
{
    extern __shared__ uint32_t smw[];
    const int tid = threadIdx.x, wid = tid >> 5, lane = tid & 31;
    const int g = lane >> 2, tg = lane & 3;
    const int bm = blockIdx.y * 128, bn = blockIdx.x * 64;
    const int wm = wid & 1, wn = wid >> 1;

    float c[4][4][4];
#pragma unroll
    for (int mi = 0; mi < 4; mi++)
#pragma unroll
        for (int ni = 0; ni < 4; ni++)
#pragma unroll
            for (int e = 0; e < 4; e++) c[mi][ni][e] = 0.f;

    float2 a_st[4][4];
    float2 b_st[4][2];

    const float* Abase = A + (long)bm * lda;
    const float* Bbase = B + (long)bn * ldb;
    const int nchunk = K >> 5;

    auto ldg_chunk = [&](int c0) {
#pragma unroll
        for (int i = 0; i < 4; i++) {
            const int gA = wid * 4 + i;
            const int mt = gA >> 1, ks = gA & 1;
            const float* ap = Abase + (long)(mt * 16 + g) * lda + c0 + ks * 16 + 2 * tg;
            a_st[i][0] = *(const float2*)ap;
            a_st[i][1] = *(const float2*)(ap + 8 * lda);
            a_st[i][2] = *(const float2*)(ap + 8);
            a_st[i][3] = *(const float2*)(ap + 8 * lda + 8);
        }
#pragma unroll
        for (int i = 0; i < 4; i++) {
            const int gB = wid * 4 + i;
            const int nt = gB >> 1, ks = gB & 1;
            const float* bp = Bbase + (long)(nt * 8 + g) * ldb + c0 + ks * 16 + 2 * tg;
            b_st[i][0] = *(const float2*)bp;
            b_st[i][1] = *(const float2*)(bp + 8);
        }
    };

    auto cvt_sts = [&](uint32_t* buf) {
#pragma unroll
        for (int i = 0; i < 4; i++) {
            const int gA = wid * 4 + i;
            uint32_t h0, h1, h2, h3, l0, l1, l2, l3;
            split_pair(a_st[i][0].x, a_st[i][0].y, h0, l0);
            split_pair(a_st[i][1].x, a_st[i][1].y, h1, l1);
            split_pair(a_st[i][2].x, a_st[i][2].y, h2, l2);
            split_pair(a_st[i][3].x, a_st[i][3].y, h3, l3);
            *(uint4*)(buf + gA * 128 + lane * 4) = make_uint4(h0, h1, h2, h3);
            *(uint4*)(buf + 2048 + gA * 128 + lane * 4) = make_uint4(l0, l1, l2, l3);
        }
#pragma unroll
        for (int i = 0; i < 4; i++) {
            const int gB = wid * 4 + i;
            uint32_t h0, h1, l0, l1;
            split_pair(b_st[i][0].x, b_st[i][0].y, h0, l0);
            split_pair(b_st[i][1].x, b_st[i][1].y, h1, l1);
            *(uint2*)(buf + 4096 + gB * 64 + lane * 2) = make_uint2(h0, h1);
            *(uint2*)(buf + 5120 + gB * 64 + lane * 2) = make_uint2(l0, l1);
        }
    };

    auto mma_chunk = [&](const uint32_t* buf) {
#pragma unroll
        for (int ks = 0; ks < 2; ks++) {
            uint4 ah[4], al[4];
            uint2 bh[4], bl[4];
#pragma unroll
            for (int mi = 0; mi < 4; mi++) {
                const int mt = wm * 4 + mi;
                ah[mi] = *(const uint4*)(buf + (mt * 2 + ks) * 128 + lane * 4);
                al[mi] = *(const uint4*)(buf + 2048 + (mt * 2 + ks) * 128 + lane * 4);
            }
#pragma unroll
            for (int ni = 0; ni < 4; ni++) {
                const int nt = wn * 4 + ni;
                bh[ni] = *(const uint2*)(buf + 4096 + (nt * 2 + ks) * 64 + lane * 2);
                bl[ni] = *(const uint2*)(buf + 5120 + (nt * 2 + ks) * 64 + lane * 2);
            }
#pragma unroll
            for (int mi = 0; mi < 4; mi++)
#pragma unroll
                for (int ni = 0; ni < 4; ni++)
                    mma16(c[mi][ni], ah[mi].x, ah[mi].y, ah[mi].z, ah[mi].w,
                          bh[ni].x, bh[ni].y);
#pragma unroll
            for (int mi = 0; mi < 4; mi++)
#pragma unroll
                for (int ni = 0; ni < 4; ni++)
                    mma16(c[mi][ni], ah[mi].x, ah[mi].y, ah[mi].z, ah[mi].w,
                          bl[ni].x, bl[ni].y);
#pragma unroll
            for (int mi = 0; mi < 4; mi++)
#pragma unroll
                for (int ni = 0; ni < 4; ni++)
                    mma16(c[mi][ni], al[mi].x, al[mi].y, al[mi].z, al[mi].w,
                          bh[ni].x, bh[ni].y);
        }
    };

    ldg_chunk(0);
    cvt_sts(smw);
    __syncthreads();
    for (int cc = 0; cc < nchunk; cc++) {
        if (cc + 1 < nchunk) ldg_chunk((cc + 1) << 5);
        mma_chunk(smw + (cc & 1) * 6144);
        if (cc + 1 < nchunk) cvt_sts(smw + ((cc + 1) & 1) * 6144);
        __syncthreads();
    }

    // ---- epilogue ----
    const int bb = bm >> 11;
#pragma unroll
    for (int mi = 0; mi < 4; mi++) {
        const int row = bm + (wm * 4 + mi) * 16 + g;
#pragma unroll
        for (int ni = 0; ni < 4; ni++) {
            const int col = bn + wn * 32 + ni * 8 + 2 * tg;
            float2 v0 = make_float2(c[mi][ni][0], c[mi][ni][1]);
            float2 v1 = make_float2(c[mi][ni][2], c[mi][ni][3]);
            if (colBias) {
                float2 cb = *(const float2*)(colBias + col);
                v0.x += cb.x; v0.y += cb.y;
                v1.x += cb.x; v1.y += cb.y;
            }
            if (batchBias) {
                float2 pb = *(const float2*)(batchBias + (long)bb * N + col);
                v0.x += pb.x; v0.y += pb.y;
                v1.x += pb.x; v1.y += pb.y;
            }
            float* g0 = C + (long)row * N + col;
            float* g1 = C + (long)(row + 8) * N + col;
            if (ACCUM) {
                float2 o0 = *(const float2*)g0;
                float2 o1 = *(const float2*)g1;
                v0.x += o0.x; v0.y += o0.y;
                v1.x += o1.x; v1.y += o1.y;
            }
            if (RELU) {
                v0.x = fmaxf(v0.x, 0.f); v0.y = fmaxf(v0.y, 0.f);
                v1.x = fmaxf(v1.x, 0.f); v1.y = fmaxf(v1.y, 0.f);
            }
            *(float2*)g0 = v0;
            *(float2*)g1 = v1;
        }
    }
}

// ============= flash attention, 3xFP16 mma =======================================
// grid=(NB/64, B*H), 128 threads (4 warps x 16 q-rows). KV tiles of 64 keys.
// smem per buffer (words): Kh[2048] Kl[2048] Vh[2048] Vl[2048]; double buffered.
#define FLASH_SMEM (2 * 8192 * 4)
__global__ void __launch_bounds__(128, 2) flash_kernel(
    const float* __restrict__ Q, const float* __restrict__ KV, float* __restrict__ O)
{
    extern __shared__ uint32_t smw[];
    const int tid = threadIdx.x, wid = tid >> 5, lane = tid & 31;
    const int g = lane >> 2, tg = lane & 3;
    const int bh = blockIdx.y, b = bh >> 4, h = bh & 15;
    const int q0 = blockIdx.x * 64;
    const int qrow = q0 + wid * 16;

    // Q fragments (hi/lo), 4 k-steps over HD=64
    uint32_t Qh[4][4], Ql[4][4];
    {
        const float* qb = Q + (long)(b * NB_ + qrow + g) * D_ + h * 64;
#pragma unroll
        for (int ks = 0; ks < 4; ks++) {
            const float* qp = qb + ks * 16 + 2 * tg;
            float2 p0 = *(const float2*)qp;
            float2 p1 = *(const float2*)(qp + 8 * D_);
            float2 p2 = *(const float2*)(qp + 8);
            float2 p3 = *(const float2*)(qp + 8 * D_ + 8);
            split_pair(p0.x, p0.y, Qh[ks][0], Ql[ks][0]);
            split_pair(p1.x, p1.y, Qh[ks][1], Ql[ks][1]);
            split_pair(p2.x, p2.y, Qh[ks][2], Ql[ks][2]);
            split_pair(p3.x, p3.y, Qh[ks][3], Ql[ks][3]);
        }
    }

    float m0 = -1e30f, m1 = -1e30f, l0 = 0.f, l1 = 0.f;
    float o[8][4];
#pragma unroll
    for (int nt = 0; nt < 8; nt++)
#pragma unroll
        for (int e = 0; e < 4; e++) o[nt][e] = 0.f;

    const float* kvb = KV + (long)b * NCTX * 2048 + h * 64;

    for (int kt = 0; kt < NCTX; kt += 64) {
        uint32_t* buf = smw + ((kt >> 6) & 1) * 8192;

        // ---- stage K (fragment layout, hi/lo) ----
#pragma unroll
        for (int i = 0; i < 8; i++) {
            const int gk = wid * 8 + i;
            const int nt = gk >> 2, ks = gk & 3;
            const float* kp = kvb + (long)(kt + nt * 8 + g) * 2048 + ks * 16 + 2 * tg;
            float2 c0 = *(const float2*)kp;
            float2 c1 = *(const float2*)(kp + 8);
            uint32_t h0, h1, w0, w1;
            split_pair(c0.x, c0.y, h0, w0);
            split_pair(c1.x, c1.y, h1, w1);
            *(uint2*)(buf + gk * 64 + lane * 2) = make_uint2(h0, h1);
            *(uint2*)(buf + 2048 + gk * 64 + lane * 2) = make_uint2(w0, w1);
        }
        // ---- stage V ----
#pragma unroll
        for (int i = 0; i < 8; i++) {
            const int gv = wid * 8 + i;
            const int nt = gv >> 2, ks = gv & 3;
            const float* vp = kvb + (long)(kt + ks * 16 + 2 * tg) * 2048 + 1024 + nt * 8 + g;
            float v00 = vp[0], v01 = vp[2048];
            float v10 = vp[8 * 2048], v11 = vp[9 * 2048];
            uint32_t h0, h1, w0, w1;
            split_pair(v00, v01, h0, w0);
            split_pair(v10, v11, h1, w1);
            *(uint2*)(buf + 4096 + gv * 64 + lane * 2) = make_uint2(h0, h1);
            *(uint2*)(buf + 6144 + gv * 64 + lane * 2) = make_uint2(w0, w1);
        }
        __syncthreads();

        // ---- QK^T ----
        float S[8][4];
#pragma unroll
        for (int nt = 0; nt < 8; nt++)
#pragma unroll
            for (int e = 0; e < 4; e++) S[nt][e] = 0.f;

#pragma unroll
        for (int ks = 0; ks < 4; ks++) {
            uint2 kh[8], kl[8];
#pragma unroll
            for (int nt = 0; nt < 8; nt++)
                kh[nt] = *(const uint2*)(buf + (nt * 4 + ks) * 64 + lane * 2);
#pragma unroll
            for (int nt = 0; nt < 8; nt++)
                kl[nt] = *(const uint2*)(buf + 2048 + (nt * 4 + ks) * 64 + lane * 2);
#pragma unroll
            for (int nt = 0; nt < 8; nt++)
                mma16(S[nt], Qh[ks][0], Qh[ks][1], Qh[ks][2], Qh[ks][3],
                      kh[nt].x, kh[nt].y);
#pragma unroll
            for (int nt = 0; nt < 8; nt++)
                mma16(S[nt], Qh[ks][0], Qh[ks][1], Qh[ks][2], Qh[ks][3],
                      kl[nt].x, kl[nt].y);
#pragma unroll
            for (int nt = 0; nt < 8; nt++)
                mma16(S[nt], Ql[ks][0], Ql[ks][1], Ql[ks][2], Ql[ks][3],
                      kh[nt].x, kh[nt].y);
        }

        // ---- online softmax (rows g / g+8; quad reduce over tg) ----
        float mx0 = -1e30f, mx1 = -1e30f;
#pragma unroll
        for (int nt = 0; nt < 8; nt++) {
            S[nt][0] *= 0.125f; S[nt][1] *= 0.125f;
            S[nt][2] *= 0.125f; S[nt][3] *= 0.125f;
            mx0 = fmaxf(mx0, fmaxf(S[nt][0], S[nt][1]));
            mx1 = fmaxf(mx1, fmaxf(S[nt][2], S[nt][3]));
        }
        mx0 = fmaxf(mx0, __shfl_xor_sync(0xffffffffu, mx0, 1));
        mx0 = fmaxf(mx0, __shfl_xor_sync(0xffffffffu, mx0, 2));
        mx1 = fmaxf(mx1, __shfl_xor_sync(0xffffffffu, mx1, 1));
        mx1 = fmaxf(mx1, __shfl_xor_sync(0xffffffffu, mx1, 2));
        const float mn0 = fmaxf(m0, mx0), mn1 = fmaxf(m1, mx1);
        const float al0 = expf(m0 - mn0), al1 = expf(m1 - mn1);
        m0 = mn0; m1 = mn1;
        float s0 = 0.f, s1 = 0.f;
#pragma unroll
        for (int nt = 0; nt < 8; nt++) {
            S[nt][0] = expf(S[nt][0] - mn0); s0 += S[nt][0];
            S[nt][1] = expf(S[nt][1] - mn0); s0 += S[nt][1];
            S[nt][2] = expf(S[nt][2] - mn1); s1 += S[nt][2];
            S[nt][3] = expf(S[nt][3] - mn1); s1 += S[nt][3];
        }
        s0 += __shfl_xor_sync(0xffffffffu, s0, 1);
        s0 += __shfl_xor_sync(0xffffffffu, s0, 2);
        s1 += __shfl_xor_sync(0xffffffffu, s1, 1);
        s1 += __shfl_xor_sync(0xffffffffu, s1, 2);
        l0 = l0 * al0 + s0;
        l1 = l1 * al1 + s1;
#pragma unroll
        for (int nt = 0; nt < 8; nt++) {
            o[nt][0] *= al0; o[nt][1] *= al0;
            o[nt][2] *= al1; o[nt][3] *= al1;
        }

        // ---- P (C-fragment of QK) -> A-fragments for PV, hi/lo ----
        uint32_t Ph[4][4], Pl[4][4];
#pragma unroll
        for (int ks = 0; ks < 4; ks++) {
            split_pair(S[2 * ks][0], S[2 * ks][1], Ph[ks][0], Pl[ks][0]);
            split_pair(S[2 * ks][2], S[2 * ks][3], Ph[ks][1], Pl[ks][1]);
            split_pair(S[2 * ks + 1][0], S[2 * ks + 1][1], Ph[ks][2], Pl[ks][2]);
            split_pair(S[2 * ks + 1][2], S[2 * ks + 1][3], Ph[ks][3], Pl[ks][3]);
        }

        // ---- P V ----
#pragma unroll
        for (int ks = 0; ks < 4; ks++) {
            uint2 vh[8], vl[8];
#pragma unroll
            for (int nt = 0; nt < 8; nt++)
                vh[nt] = *(const uint2*)(buf + 4096 + (nt * 4 + ks) * 64 + lane * 2);
#pragma unroll
            for (int nt = 0; nt < 8; nt++)
                vl[nt] = *(const uint2*)(buf + 6144 + (nt * 4 + ks) * 64 + lane * 2);
#pragma unroll
            for (int nt = 0; nt < 8; nt++)
                mma16(o[nt], Ph[ks][0], Ph[ks][1], Ph[ks][2], Ph[ks][3],
                      vh[nt].x, vh[nt].y);
#pragma unroll
            for (int nt = 0; nt < 8; nt++)
                mma16(o[nt], Ph[ks][0], Ph[ks][1], Ph[ks][2], Ph[ks][3],
                      vl[nt].x, vl[nt].y);
#pragma unroll
            for (int nt = 0; nt < 8; nt++)
                mma16(o[nt], Pl[ks][0], Pl[ks][1], Pl[ks][2], Pl[ks][3],
                      vh[nt].x, vh[nt].y);
        }
    }

    const float inv0 = 1.0f / l0, inv1 = 1.0f / l1;
    float* op = O + (long)(b * NB_ + qrow + g) * D_ + h * 64;
#pragma unroll
    for (int nt = 0; nt < 8; nt++) {
        *(float2*)(op + nt * 8 + 2 * tg) =
            make_float2(o[nt][0] * inv0, o[nt][1] * inv0);
        *(float2*)(op + 8 * D_ + nt * 8 + 2 * tg) =
            make_float2(o[nt][2] * inv1, o[nt][3] * inv1);
    }
}

// ---------------- residual + layernorm ------------------------------------------
__global__ void __launch_bounds__(256) ln_kernel(
    const float* __restrict__ X, const float* __restrict__ R,
    const float* __restrict__ gam, const float* __restrict__ bet, float* __restrict__ Y)
{
    __shared__ float red[8];
    const int row = blockIdx.x, tid = threadIdx.x;
    const float* x = X + (long)row * D_;
    const float* rr = R + (long)row * D_;
    float v[4];
    float s = 0.f;
#pragma unroll
    for (int i = 0; i < 4; i++) {
        int c = tid + 256 * i;
        v[i] = x[c] + rr[c];
        s += v[i];
    }
#pragma unroll
    for (int off = 16; off > 0; off >>= 1) s += __shfl_xor_sync(0xffffffffu, s, off);
    if ((tid & 31) == 0) red[tid >> 5] = s;
    __syncthreads();
    float tot = red[0] + red[1] + red[2] + red[3] + red[4] + red[5] + red[6] + red[7];
    float mu = tot * (1.0f / 1024.0f);
    __syncthreads();
    float s2 = 0.f;
#pragma unroll
    for (int i = 0; i < 4; i++) { float d = v[i] - mu; s2 += d * d; }
#pragma unroll
    for (int off = 16; off > 0; off >>= 1) s2 += __shfl_xor_sync(0xffffffffu, s2, off);
    if ((tid & 31) == 0) red[tid >> 5] = s2;
    __syncthreads();
    float tot2 = red[0] + red[1] + red[2] + red[3] + red[4] + red[5] + red[6] + red[7];
    float rstd = rsqrtf(tot2 * (1.0f / 1024.0f) + 1e-5f);
#pragma unroll
    for (int i = 0; i < 4; i++) {
        int c = tid + 256 * i;
        Y[(long)row * D_ + c] = (v[i] - mu) * rstd * gam[c] + bet[c];
    }
}

// ---------------- generic warp-dot: Y[b][j] = act(dot(X[b], W[j]) + b1 + b2) ------
template <int ACT>
__global__ void __launch_bounds__(256) rowdot(
    const float* __restrict__ X, const float* __restrict__ W, int ldw,
    const float* __restrict__ b1, const float* __restrict__ b2,
    float* __restrict__ Y, int Kd, int J)
{
    const int b = blockIdx.x;
    const int w = threadIdx.x >> 5, lane = threadIdx.x & 31;
    const int j = blockIdx.y * 8 + w;
    const float* x = X + (long)b * Kd;
    const float* wr = W + (long)j * ldw;
    float s = 0.f;
    for (int k = lane * 4; k < Kd; k += 128) {
        float4 xv = *(const float4*)(x + k);
        float4 wv = *(const float4*)(wr + k);
        s += xv.x * wv.x + xv.y * wv.y + xv.z * wv.z + xv.w * wv.w;
    }
#pragma unroll
    for (int off = 16; off > 0; off >>= 1) s += __shfl_xor_sync(0xffffffffu, s, off);
    if (lane == 0) {
        if (b1) s += b1[j];
        if (b2) s += b2[j];
        if (ACT == 1) s = s / (1.f + expf(-s));
        Y[(long)b * J + j] = s;
    }
}

// ---------------- small kernels ---------------------------------------------------
__global__ void emb_kernel(const int* __restrict__ t)
{
    const int b = blockIdx.x, i = threadIdx.x;
    float fr = expf(-9.2103403719761836f * (float)i / 511.0f);
    float arg = (float)t[b] * fr;
    g_emb[b * D_ + i] = sinf(arg);
    g_emb[b * D_ + 512 + i] = cosf(arg);
}

__global__ void __launch_bounds__(256) concat_kernel(
    const float* __restrict__ A, const float* __restrict__ C)
{
    const int row = blockIdx.x;
    const int b = row >> 11, j = row & 2047;
    const float* src = (j < 1024) ? (A + ((long)b * 1024 + j) * D_)
                                  : (C + ((long)b * 1024 + (j - 1024)) * D_);
    float4* dst = (float4*)(g_ctxAC + (long)row * D_);
    dst[threadIdx.x] = ((const float4*)src)[threadIdx.x];
}

__global__ void __launch_bounds__(256) router_kernel(
    const float* __restrict__ logits, const int* __restrict__ t,
    float* __restrict__ dispatch, float* __restrict__ combine, float* __restrict__ loadp)
{
    __shared__ float sd[8 * 256];
    const int tid = threadIdx.x;
    const int tok = blockIdx.x * 256 + tid;
    const int b = tok >> 11;
    const float tn = (float)t[b] * 0.001f;
    const float tau_inv = 1.0f / (0.5f + 1.5f * tn);

    float p[8];
    float mx = -1e30f;
#pragma unroll
    for (int e = 0; e < 8; e++) { p[e] = logits[tok * 8 + e] * tau_inv; mx = fmaxf(mx, p[e]); }
    float s = 0.f;
#pragma unroll
    for (int e = 0; e < 8; e++) { p[e] = expf(p[e] - mx); s += p[e]; }
    float inv = 1.0f / s;
#pragma unroll
    for (int e = 0; e < 8; e++) p[e] = 0.85f * (p[e] * inv) + 0.01875f;

    const float w = 0.1f + 0.1f * tn;
    float sh = fmaxf(p[0], w);
    float os = 0.f;
#pragma unroll
    for (int e = 1; e < 8; e++) os += p[e];
    float sc = (1.0f - sh) / fmaxf(os, 1e-8f);
    p[0] = sh;
#pragma unroll
    for (int e = 1; e < 8; e++) p[e] *= sc;

    int i1 = 0; float v1 = p[0];
#pragma unroll
    for (int e = 1; e < 8; e++) if (p[e] > v1) { v1 = p[e]; i1 = e; }
    int i2 = -1; float v2 = -1e30f;
#pragma unroll
    for (int e = 0; e < 8; e++) if (e != i1 && p[e] > v2) { v2 = p[e]; i2 = e; }

    float d[8];
#pragma unroll
    for (int e = 0; e < 8; e++) d[e] = 0.f;
    d[i1] = v1; d[i2] = v2;

    const float cap = 0.5f + 0.1f * tn;
    float ext = 0.f, hs = 0.f;
    float hd[8];
#pragma unroll
    for (int e = 0; e < 8; e++) {
        float ex = fmaxf(d[e] - cap, 0.f);
        d[e] -= ex; ext += ex;
        hd[e] = fmaxf(cap - d[e], 0.f); hs += hd[e];
    }
    hs = fmaxf(hs, 1e-8f);
    float ds = 0.f;
#pragma unroll
    for (int e = 0; e < 8; e++) { d[e] += ext * (hd[e] / hs); ds += d[e]; }
    float ci = 1.0f / (ds + 1e-8f);
#pragma unroll
    for (int e = 0; e < 8; e++) {
        dispatch[tok * 8 + e] = d[e];
        combine[tok * 8 + e] = d[e] * ci;
        sd[e * 256 + tid] = d[e];
    }
    __syncthreads();
    if (tid < 8) {
        float acc = 0.f;
        for (int i = 0; i < 256; i++) acc += sd[tid * 256 + i];
        loadp[blockIdx.x * 8 + tid] = acc;
    }
}

__global__ void penalty_kernel(const float* __restrict__ loadp, float* __restrict__ out)
{
    if (threadIdx.x == 0) {
        const float thr = (2048.0f / 7.0f) * 1.5f;
        float pen = 0.f;
        for (int e = 1; e < 8; e++) {
            float l = 0.f;
            for (int blk = 0; blk < 32; blk++) l += loadp[blk * 8 + e];
            l *= 0.25f;
            float x = l - thr;
            if (x > 0.f) pen += x * x;
        }
        out[0] = 0.01f * pen;
    }
}

// ---------------- launch ----------------------------------------------------------
extern "C" void kernel_launch(void* const* d_in, const int* in_sizes, int n_in,
                              void* d_out, int out_size)
{
    const float* tokens = (const float*)d_in[0];
    const float* outA   = (const float*)d_in[1];
    const float* outC   = (const float*)d_in[2];
    const int*   t      = (const int*)d_in[3];
    const float* in_w   = (const float*)d_in[4];
    const float* in_b   = (const float*)d_in[5];
    const float* op_w   = (const float*)d_in[6];
    const float* op_b   = (const float*)d_in[7];
    const float* lng    = (const float*)d_in[8];
    const float* lnb    = (const float*)d_in[9];
    const float* te_w1  = (const float*)d_in[10];
    const float* te_b1  = (const float*)d_in[11];
    const float* te_w2  = (const float*)d_in[12];
    const float* te_b2  = (const float*)d_in[13];
    const float* gw1    = (const float*)d_in[14];
    const float* gb1    = (const float*)d_in[15];
    const float* gw2    = (const float*)d_in[16];
    const float* gb2    = (const float*)d_in[17];
    const float* ebias  = (const float*)d_in[18];
    float* out = (float*)d_out;

    float *p_ctxAC, *p_q, *p_kv, *p_attn, *p_proj, *p_ctxB, *p_hidden,
          *p_logits, *p_emb, *p_h2, *p_temb, *p_tec, *p_loadp;
    cudaGetSymbolAddress((void**)&p_ctxAC, g_ctxAC);
    cudaGetSymbolAddress((void**)&p_q, g_q);
    cudaGetSymbolAddress((void**)&p_kv, g_kv);
    cudaGetSymbolAddress((void**)&p_attn, g_attn);
    cudaGetSymbolAddress((void**)&p_proj, g_proj);
    cudaGetSymbolAddress((void**)&p_ctxB, g_ctxB);
    cudaGetSymbolAddress((void**)&p_hidden, g_hidden);
    cudaGetSymbolAddress((void**)&p_logits, g_logits);
    cudaGetSymbolAddress((void**)&p_emb, g_emb);
    cudaGetSymbolAddress((void**)&p_h2, g_h2);
    cudaGetSymbolAddress((void**)&p_temb, g_temb);
    cudaGetSymbolAddress((void**)&p_tec, g_tec);
    cudaGetSymbolAddress((void**)&p_loadp, g_loadp);

    cudaFuncSetAttribute(flash_kernel, cudaFuncAttributeMaxDynamicSharedMemorySize,
                         FLASH_SMEM);
    cudaFuncSetAttribute(hgemm_nt<false, false>,
                         cudaFuncAttributeMaxDynamicSharedMemorySize, HGEMM_SMEM);
    cudaFuncSetAttribute(hgemm_nt<true, true>,
                         cudaFuncAttributeMaxDynamicSharedMemorySize, HGEMM_SMEM);

    // ---- time embedding chain ----
    emb_kernel<<<BATCH, 512>>>(t);
    rowdot<1><<<dim3(BATCH, 256), 256>>>(p_emb, te_w1, 1024, te_b1, nullptr, p_h2, 1024, 2048);
    rowdot<0><<<dim3(BATCH, 128), 256>>>(p_h2, te_w2, 2048, te_b2, nullptr, p_temb, 2048, 1024);
    rowdot<0><<<dim3(BATCH, 128), 256>>>(p_temb, gw1 + 2048, 3072, gb1, nullptr, p_tec, 1024, 1024);

    // ---- attention path ----
    concat_kernel<<<NTOK, 256>>>(outA, outC);
    hgemm_nt<false, false><<<dim3(16, 64), 128, HGEMM_SMEM>>>(
        1024, 1024, tokens, 1024, in_w, 1024, p_q, in_b, nullptr);
    hgemm_nt<false, false><<<dim3(32, 64), 128, HGEMM_SMEM>>>(
        2048, 1024, p_ctxAC, 1024, in_w + 1024 * 1024, 1024, p_kv, in_b + 1024, nullptr);
    flash_kernel<<<dim3(32, BATCH * H_), 128, FLASH_SMEM>>>(p_q, p_kv, p_attn);
    hgemm_nt<false, false><<<dim3(16, 64), 128, HGEMM_SMEM>>>(
        1024, 1024, p_attn, 1024, op_w, 1024, p_proj, op_b, nullptr);
    ln_kernel<<<NTOK, 256>>>(p_proj, tokens, lng, lnb, p_ctxB);

    // ---- gate hidden ----
    hgemm_nt<false, false><<<dim3(16, 64), 128, HGEMM_SMEM>>>(
        1024, 1024, tokens, 1024, gw1, 3072, p_hidden, nullptr, p_tec);
    hgemm_nt<true, true><<<dim3(16, 64), 128, HGEMM_SMEM>>>(
        1024, 1024, p_ctxB, 1024, gw1 + 1024, 3072, p_hidden, nullptr, nullptr);

    // ---- logits + routing ----
    rowdot<0><<<dim3(NTOK, 1), 256>>>(p_hidden, gw2, 1024, gb2, ebias, p_logits, 1024, 8);
    router_kernel<<<32, 256>>>(p_logits, t, out, out + 65536, p_loadp);
    penalty_kernel<<<1, 32>>>(p_loadp, out + 2 * 65536);
}